// round 1
// baseline (speedup 1.0000x reference)
#include <cuda_runtime.h>

#define B_   16
#define C_   512
#define D_   512
#define N1_  2048
#define N2_  2048
#define TILE 128
#define KB   16

// ---------------------------------------------------------------------------
// Packed f32x2 helpers (FFMA2 is only reachable via PTX on sm_103a)
// ---------------------------------------------------------------------------
__device__ __forceinline__ unsigned long long pack2(float x) {
    unsigned long long r;
    asm("mov.b64 %0, {%1, %1};" : "=l"(r) : "r"(__float_as_uint(x)));
    return r;
}
__device__ __forceinline__ void ffma2(unsigned long long &d,
                                      unsigned long long a,
                                      unsigned long long b) {
    asm("fma.rn.f32x2 %0, %1, %2, %0;" : "+l"(d) : "l"(a), "l"(b));
}

// ---------------------------------------------------------------------------
// GEMM1: S[b][n2][n1] = sum_c RI2[b][c][n2] * RI1[b][c][n1]
// Both operands K-major in GMEM (k = c has stride N), rows contiguous.
// ---------------------------------------------------------------------------
__global__ __launch_bounds__(256, 2)
void gemm1_kernel(const float* __restrict__ RI1,
                  const float* __restrict__ RI2,
                  float* __restrict__ S)
{
    __shared__ __align__(16) float As[KB][TILE];   // [c][n2 tile]
    __shared__ __align__(16) float Bs[KB][TILE];   // [c][n1 tile]

    const int b    = blockIdx.z;
    const int n2_0 = blockIdx.y * TILE;
    const int n1_0 = blockIdx.x * TILE;
    const int t    = threadIdx.x;

    const float* Ag = RI2 + (size_t)b * C_ * N2_ + n2_0;
    const float* Bg = RI1 + (size_t)b * C_ * N1_ + n1_0;

    const int lrow = t >> 5;          // 0..7 (and +8)
    const int lcol = (t & 31) * 4;

    // prefetch kb = 0
    float4 pa0 = *(const float4*)(Ag + (size_t)(lrow    ) * N2_ + lcol);
    float4 pa1 = *(const float4*)(Ag + (size_t)(lrow + 8) * N2_ + lcol);
    float4 pb0 = *(const float4*)(Bg + (size_t)(lrow    ) * N1_ + lcol);
    float4 pb1 = *(const float4*)(Bg + (size_t)(lrow + 8) * N1_ + lcol);

    const int tm8 = (t >> 4) * 8;     // row block within tile (n2)
    const int tn8 = (t & 15) * 8;     // col block within tile (n1)

    unsigned long long acc[8][4];
    #pragma unroll
    for (int i = 0; i < 8; i++)
        #pragma unroll
        for (int j = 0; j < 4; j++) acc[i][j] = 0ULL;

    for (int kb = 0; kb < C_; kb += KB) {
        *(float4*)&As[lrow    ][lcol] = pa0;
        *(float4*)&As[lrow + 8][lcol] = pa1;
        *(float4*)&Bs[lrow    ][lcol] = pb0;
        *(float4*)&Bs[lrow + 8][lcol] = pb1;
        __syncthreads();

        if (kb + KB < C_) {
            const float* Agn = Ag + (size_t)(kb + KB) * N2_;
            const float* Bgn = Bg + (size_t)(kb + KB) * N1_;
            pa0 = *(const float4*)(Agn + (size_t)(lrow    ) * N2_ + lcol);
            pa1 = *(const float4*)(Agn + (size_t)(lrow + 8) * N2_ + lcol);
            pb0 = *(const float4*)(Bgn + (size_t)(lrow    ) * N1_ + lcol);
            pb1 = *(const float4*)(Bgn + (size_t)(lrow + 8) * N1_ + lcol);
        }

        #pragma unroll
        for (int k = 0; k < KB; k++) {
            float4 a0 = *(const float4*)&As[k][tm8];
            float4 a1 = *(const float4*)&As[k][tm8 + 4];
            unsigned long long bv0 = *(const unsigned long long*)&Bs[k][tn8    ];
            unsigned long long bv1 = *(const unsigned long long*)&Bs[k][tn8 + 2];
            unsigned long long bv2 = *(const unsigned long long*)&Bs[k][tn8 + 4];
            unsigned long long bv3 = *(const unsigned long long*)&Bs[k][tn8 + 6];
            float af[8] = {a0.x, a0.y, a0.z, a0.w, a1.x, a1.y, a1.z, a1.w};
            #pragma unroll
            for (int i = 0; i < 8; i++) {
                unsigned long long ai = pack2(af[i]);
                ffma2(acc[i][0], ai, bv0);
                ffma2(acc[i][1], ai, bv1);
                ffma2(acc[i][2], ai, bv2);
                ffma2(acc[i][3], ai, bv3);
            }
        }
        __syncthreads();
    }

    float* Crow = S + (size_t)b * N2_ * N1_ + (size_t)(n2_0 + tm8) * N1_ + n1_0 + tn8;
    #pragma unroll
    for (int i = 0; i < 8; i++) {
        unsigned long long* cp = (unsigned long long*)(Crow + (size_t)i * N1_);
        cp[0] = acc[i][0]; cp[1] = acc[i][1]; cp[2] = acc[i][2]; cp[3] = acc[i][3];
    }
}

// ---------------------------------------------------------------------------
// Softmax over n2 for each (b, n1) column, in place.
// Thread per column; adjacent threads = adjacent n1 -> coalesced.
// ---------------------------------------------------------------------------
__global__ void softmax_kernel(float* __restrict__ S)
{
    const int idx = blockIdx.x * blockDim.x + threadIdx.x;
    const int b  = idx >> 11;           // / N1_
    const int n1 = idx & (N1_ - 1);
    float* col = S + (size_t)b * N2_ * N1_ + n1;

    float m = -3.402823466e38f;
    float s = 0.0f;
    #pragma unroll 4
    for (int n2 = 0; n2 < N2_; n2++) {
        float x  = col[(size_t)n2 * N1_];
        float mn = fmaxf(m, x);
        s = s * __expf(m - mn) + __expf(x - mn);
        m = mn;
    }
    const float inv = 1.0f / s;
    #pragma unroll 4
    for (int n2 = 0; n2 < N2_; n2++) {
        float x = col[(size_t)n2 * N1_];
        col[(size_t)n2 * N1_] = __expf(x - m) * inv;
    }
}

// ---------------------------------------------------------------------------
// GEMM2: O[b][d][n1] = sum_n2 RE2[b][d][n2] * A[b][n2][n1]
// RE2 rows are k-contiguous -> transpose into shared at load time.
// ---------------------------------------------------------------------------
__global__ __launch_bounds__(256, 2)
void gemm2_kernel(const float* __restrict__ RE2,
                  const float* __restrict__ A,
                  float* __restrict__ O)
{
    __shared__ __align__(16) float As2[KB][TILE];  // [k][d tile]
    __shared__ __align__(16) float Bs2[KB][TILE];  // [k][n1 tile]

    const int b    = blockIdx.z;
    const int d0   = blockIdx.y * TILE;
    const int n1_0 = blockIdx.x * TILE;
    const int t    = threadIdx.x;

    // RE2 transposing loader: warp covers 32 consecutive d rows, same k-half.
    const int ld  = t & 127;
    const int lkh = (t >> 7) * 8;
    const float* Ag = RE2 + (size_t)b * D_ * N2_ + (size_t)(d0 + ld) * N2_ + lkh;

    // attention tile loader (rows contiguous)
    const int lrow = t >> 5;
    const int lcol = (t & 31) * 4;
    const float* Bg = A + (size_t)b * N2_ * N1_ + n1_0;

    float4 pa0 = *(const float4*)(Ag + 0);
    float4 pa1 = *(const float4*)(Ag + 4);
    float4 pb0 = *(const float4*)(Bg + (size_t)(lrow    ) * N1_ + lcol);
    float4 pb1 = *(const float4*)(Bg + (size_t)(lrow + 8) * N1_ + lcol);

    const int tm8 = (t >> 4) * 8;     // d block
    const int tn8 = (t & 15) * 8;     // n1 block

    unsigned long long acc[8][4];
    #pragma unroll
    for (int i = 0; i < 8; i++)
        #pragma unroll
        for (int j = 0; j < 4; j++) acc[i][j] = 0ULL;

    for (int kb = 0; kb < N2_; kb += KB) {
        As2[lkh + 0][ld] = pa0.x;
        As2[lkh + 1][ld] = pa0.y;
        As2[lkh + 2][ld] = pa0.z;
        As2[lkh + 3][ld] = pa0.w;
        As2[lkh + 4][ld] = pa1.x;
        As2[lkh + 5][ld] = pa1.y;
        As2[lkh + 6][ld] = pa1.z;
        As2[lkh + 7][ld] = pa1.w;
        *(float4*)&Bs2[lrow    ][lcol] = pb0;
        *(float4*)&Bs2[lrow + 8][lcol] = pb1;
        __syncthreads();

        if (kb + KB < N2_) {
            const float* Agn = Ag + (kb + KB);
            const float* Bgn = Bg + (size_t)(kb + KB) * N1_;
            pa0 = *(const float4*)(Agn + 0);
            pa1 = *(const float4*)(Agn + 4);
            pb0 = *(const float4*)(Bgn + (size_t)(lrow    ) * N1_ + lcol);
            pb1 = *(const float4*)(Bgn + (size_t)(lrow + 8) * N1_ + lcol);
        }

        #pragma unroll
        for (int k = 0; k < KB; k++) {
            float4 a0 = *(const float4*)&As2[k][tm8];
            float4 a1 = *(const float4*)&As2[k][tm8 + 4];
            unsigned long long bv0 = *(const unsigned long long*)&Bs2[k][tn8    ];
            unsigned long long bv1 = *(const unsigned long long*)&Bs2[k][tn8 + 2];
            unsigned long long bv2 = *(const unsigned long long*)&Bs2[k][tn8 + 4];
            unsigned long long bv3 = *(const unsigned long long*)&Bs2[k][tn8 + 6];
            float af[8] = {a0.x, a0.y, a0.z, a0.w, a1.x, a1.y, a1.z, a1.w};
            #pragma unroll
            for (int i = 0; i < 8; i++) {
                unsigned long long ai = pack2(af[i]);
                ffma2(acc[i][0], ai, bv0);
                ffma2(acc[i][1], ai, bv1);
                ffma2(acc[i][2], ai, bv2);
                ffma2(acc[i][3], ai, bv3);
            }
        }
        __syncthreads();
    }

    float* Crow = O + (size_t)b * D_ * N1_ + (size_t)(d0 + tm8) * N1_ + n1_0 + tn8;
    #pragma unroll
    for (int i = 0; i < 8; i++) {
        unsigned long long* cp = (unsigned long long*)(Crow + (size_t)i * N1_);
        cp[0] = acc[i][0]; cp[1] = acc[i][1]; cp[2] = acc[i][2]; cp[3] = acc[i][3];
    }
}

// ---------------------------------------------------------------------------
// Launch: scores -> attn region of d_out, softmax in place, then GEMM2.
// Graph-capturable: 3 plain launches on the legacy stream, no allocs/syncs.
// ---------------------------------------------------------------------------
extern "C" void kernel_launch(void* const* d_in, const int* in_sizes, int n_in,
                              void* d_out, int out_size)
{
    (void)in_sizes; (void)n_in; (void)out_size;
    const float* RI1 = (const float*)d_in[0];   // [B][C][N1]
    const float* RI2 = (const float*)d_in[1];   // [B][C][N2]
    const float* RE2 = (const float*)d_in[2];   // [B][D][N2]

    float* out   = (float*)d_out;
    float* embed = out;                                  // [B][D][N1]
    float* attn  = out + (size_t)B_ * D_ * N1_;          // [B][N2][N1]

    dim3 g1(N1_ / TILE, N2_ / TILE, B_);
    gemm1_kernel<<<g1, 256>>>(RI1, RI2, attn);

    softmax_kernel<<<(B_ * N1_) / 256, 256>>>(attn);

    dim3 g2(N1_ / TILE, D_ / TILE, B_);
    gemm2_kernel<<<g2, 256>>>(RE2, attn, embed);
}

// round 2
// speedup vs baseline: 1.0718x; 1.0718x over previous
#include <cuda_runtime.h>

#define B_   16
#define C_   512
#define D_   512
#define N1_  2048
#define N2_  2048
#define TILE 128
#define KB   16

// ---------------------------------------------------------------------------
// Packed f32x2 helpers (FFMA2 is only reachable via PTX on sm_103a)
// ---------------------------------------------------------------------------
__device__ __forceinline__ unsigned long long pack2(float x) {
    unsigned long long r;
    asm("mov.b64 %0, {%1, %1};" : "=l"(r) : "r"(__float_as_uint(x)));
    return r;
}
__device__ __forceinline__ void ffma2(unsigned long long &d,
                                      unsigned long long a,
                                      unsigned long long b) {
    asm("fma.rn.f32x2 %0, %1, %2, %0;" : "+l"(d) : "l"(a), "l"(b));
}

// ---------------------------------------------------------------------------
// GEMM1: S[b][n2][n1] = sum_c RI2[b][c][n2] * RI1[b][c][n1]
// Double-buffered smem, one barrier per k-block.
// ---------------------------------------------------------------------------
__global__ __launch_bounds__(256, 2)
void gemm1_kernel(const float* __restrict__ RI1,
                  const float* __restrict__ RI2,
                  float* __restrict__ S)
{
    __shared__ __align__(16) float As[2][KB][TILE];   // [buf][c][n2 tile]
    __shared__ __align__(16) float Bs[2][KB][TILE];   // [buf][c][n1 tile]

    const int b    = blockIdx.z;
    const int n2_0 = blockIdx.y * TILE;
    const int n1_0 = blockIdx.x * TILE;
    const int t    = threadIdx.x;

    const float* Ag = RI2 + (size_t)b * C_ * N2_ + n2_0;
    const float* Bg = RI1 + (size_t)b * C_ * N1_ + n1_0;

    const int lrow = t >> 5;          // 0..7 (and +8)
    const int lcol = (t & 31) * 4;

    // prefetch kb = 0 and fill buffer 0
    float4 pa0 = *(const float4*)(Ag + (size_t)(lrow    ) * N2_ + lcol);
    float4 pa1 = *(const float4*)(Ag + (size_t)(lrow + 8) * N2_ + lcol);
    float4 pb0 = *(const float4*)(Bg + (size_t)(lrow    ) * N1_ + lcol);
    float4 pb1 = *(const float4*)(Bg + (size_t)(lrow + 8) * N1_ + lcol);
    *(float4*)&As[0][lrow    ][lcol] = pa0;
    *(float4*)&As[0][lrow + 8][lcol] = pa1;
    *(float4*)&Bs[0][lrow    ][lcol] = pb0;
    *(float4*)&Bs[0][lrow + 8][lcol] = pb1;
    __syncthreads();

    const int tm8 = (t >> 4) * 8;     // row block within tile (n2)
    const int tn8 = (t & 15) * 8;     // col block within tile (n1)

    unsigned long long acc[8][4];
    #pragma unroll
    for (int i = 0; i < 8; i++)
        #pragma unroll
        for (int j = 0; j < 4; j++) acc[i][j] = 0ULL;

    for (int kb = 0; kb < C_; kb += KB) {
        const int  cur  = (kb >> 4) & 1;
        const bool more = (kb + KB) < C_;

        if (more) {
            const float* Agn = Ag + (size_t)(kb + KB) * N2_;
            const float* Bgn = Bg + (size_t)(kb + KB) * N1_;
            pa0 = *(const float4*)(Agn + (size_t)(lrow    ) * N2_ + lcol);
            pa1 = *(const float4*)(Agn + (size_t)(lrow + 8) * N2_ + lcol);
            pb0 = *(const float4*)(Bgn + (size_t)(lrow    ) * N1_ + lcol);
            pb1 = *(const float4*)(Bgn + (size_t)(lrow + 8) * N1_ + lcol);
        }

        const float (* __restrict__ Ac)[TILE] = As[cur];
        const float (* __restrict__ Bc)[TILE] = Bs[cur];
        #pragma unroll
        for (int k = 0; k < KB; k++) {
            float4 a0 = *(const float4*)&Ac[k][tm8];
            float4 a1 = *(const float4*)&Ac[k][tm8 + 4];
            unsigned long long bv0 = *(const unsigned long long*)&Bc[k][tn8    ];
            unsigned long long bv1 = *(const unsigned long long*)&Bc[k][tn8 + 2];
            unsigned long long bv2 = *(const unsigned long long*)&Bc[k][tn8 + 4];
            unsigned long long bv3 = *(const unsigned long long*)&Bc[k][tn8 + 6];
            float af[8] = {a0.x, a0.y, a0.z, a0.w, a1.x, a1.y, a1.z, a1.w};
            #pragma unroll
            for (int i = 0; i < 8; i++) {
                unsigned long long ai = pack2(af[i]);
                ffma2(acc[i][0], ai, bv0);
                ffma2(acc[i][1], ai, bv1);
                ffma2(acc[i][2], ai, bv2);
                ffma2(acc[i][3], ai, bv3);
            }
        }

        if (more) {
            const int nxt = cur ^ 1;
            *(float4*)&As[nxt][lrow    ][lcol] = pa0;
            *(float4*)&As[nxt][lrow + 8][lcol] = pa1;
            *(float4*)&Bs[nxt][lrow    ][lcol] = pb0;
            *(float4*)&Bs[nxt][lrow + 8][lcol] = pb1;
        }
        __syncthreads();
    }

    float* Crow = S + (size_t)b * N2_ * N1_ + (size_t)(n2_0 + tm8) * N1_ + n1_0 + tn8;
    #pragma unroll
    for (int i = 0; i < 8; i++) {
        unsigned long long* cp = (unsigned long long*)(Crow + (size_t)i * N1_);
        cp[0] = acc[i][0]; cp[1] = acc[i][1]; cp[2] = acc[i][2]; cp[3] = acc[i][3];
    }
}

// ---------------------------------------------------------------------------
// Softmax over n2 for each (b, n1) column, in place.
// Thread per column; adjacent threads = adjacent n1 -> coalesced.
// ---------------------------------------------------------------------------
__global__ void softmax_kernel(float* __restrict__ S)
{
    const int idx = blockIdx.x * blockDim.x + threadIdx.x;
    const int b  = idx >> 11;           // / N1_
    const int n1 = idx & (N1_ - 1);
    float* col = S + (size_t)b * N2_ * N1_ + n1;

    float m = -3.402823466e38f;
    float s = 0.0f;
    #pragma unroll 8
    for (int n2 = 0; n2 < N2_; n2++) {
        float x  = col[(size_t)n2 * N1_];
        float mn = fmaxf(m, x);
        s = s * __expf(m - mn) + __expf(x - mn);
        m = mn;
    }
    const float inv = 1.0f / s;
    #pragma unroll 8
    for (int n2 = 0; n2 < N2_; n2++) {
        float x = col[(size_t)n2 * N1_];
        col[(size_t)n2 * N1_] = __expf(x - m) * inv;
    }
}

// ---------------------------------------------------------------------------
// GEMM2: O[b][d][n1] = sum_n2 RE2[b][d][n2] * A[b][n2][n1]
// RE2 rows are k-contiguous -> transpose into shared at load time.
// Double-buffered smem, one barrier per k-block.
// ---------------------------------------------------------------------------
__global__ __launch_bounds__(256, 2)
void gemm2_kernel(const float* __restrict__ RE2,
                  const float* __restrict__ A,
                  float* __restrict__ O)
{
    __shared__ __align__(16) float As2[2][KB][TILE];  // [buf][k][d tile]
    __shared__ __align__(16) float Bs2[2][KB][TILE];  // [buf][k][n1 tile]

    const int b    = blockIdx.z;
    const int d0   = blockIdx.y * TILE;
    const int n1_0 = blockIdx.x * TILE;
    const int t    = threadIdx.x;

    // RE2 transposing loader: warp covers 32 consecutive d rows, same k-half.
    const int ld  = t & 127;
    const int lkh = (t >> 7) * 8;
    const float* Ag = RE2 + (size_t)b * D_ * N2_ + (size_t)(d0 + ld) * N2_ + lkh;

    // attention tile loader (rows contiguous)
    const int lrow = t >> 5;
    const int lcol = (t & 31) * 4;
    const float* Bg = A + (size_t)b * N2_ * N1_ + n1_0;

    float4 pa0 = *(const float4*)(Ag + 0);
    float4 pa1 = *(const float4*)(Ag + 4);
    float4 pb0 = *(const float4*)(Bg + (size_t)(lrow    ) * N1_ + lcol);
    float4 pb1 = *(const float4*)(Bg + (size_t)(lrow + 8) * N1_ + lcol);

    As2[0][lkh + 0][ld] = pa0.x;
    As2[0][lkh + 1][ld] = pa0.y;
    As2[0][lkh + 2][ld] = pa0.z;
    As2[0][lkh + 3][ld] = pa0.w;
    As2[0][lkh + 4][ld] = pa1.x;
    As2[0][lkh + 5][ld] = pa1.y;
    As2[0][lkh + 6][ld] = pa1.z;
    As2[0][lkh + 7][ld] = pa1.w;
    *(float4*)&Bs2[0][lrow    ][lcol] = pb0;
    *(float4*)&Bs2[0][lrow + 8][lcol] = pb1;
    __syncthreads();

    const int tm8 = (t >> 4) * 8;     // d block
    const int tn8 = (t & 15) * 8;     // n1 block

    unsigned long long acc[8][4];
    #pragma unroll
    for (int i = 0; i < 8; i++)
        #pragma unroll
        for (int j = 0; j < 4; j++) acc[i][j] = 0ULL;

    for (int kb = 0; kb < N2_; kb += KB) {
        const int  cur  = (kb >> 4) & 1;
        const bool more = (kb + KB) < N2_;

        if (more) {
            const float* Agn = Ag + (kb + KB);
            const float* Bgn = Bg + (size_t)(kb + KB) * N1_;
            pa0 = *(const float4*)(Agn + 0);
            pa1 = *(const float4*)(Agn + 4);
            pb0 = *(const float4*)(Bgn + (size_t)(lrow    ) * N1_ + lcol);
            pb1 = *(const float4*)(Bgn + (size_t)(lrow + 8) * N1_ + lcol);
        }

        const float (* __restrict__ Ac)[TILE] = As2[cur];
        const float (* __restrict__ Bc)[TILE] = Bs2[cur];
        #pragma unroll
        for (int k = 0; k < KB; k++) {
            float4 a0 = *(const float4*)&Ac[k][tm8];
            float4 a1 = *(const float4*)&Ac[k][tm8 + 4];
            unsigned long long bv0 = *(const unsigned long long*)&Bc[k][tn8    ];
            unsigned long long bv1 = *(const unsigned long long*)&Bc[k][tn8 + 2];
            unsigned long long bv2 = *(const unsigned long long*)&Bc[k][tn8 + 4];
            unsigned long long bv3 = *(const unsigned long long*)&Bc[k][tn8 + 6];
            float af[8] = {a0.x, a0.y, a0.z, a0.w, a1.x, a1.y, a1.z, a1.w};
            #pragma unroll
            for (int i = 0; i < 8; i++) {
                unsigned long long ai = pack2(af[i]);
                ffma2(acc[i][0], ai, bv0);
                ffma2(acc[i][1], ai, bv1);
                ffma2(acc[i][2], ai, bv2);
                ffma2(acc[i][3], ai, bv3);
            }
        }

        if (more) {
            const int nxt = cur ^ 1;
            As2[nxt][lkh + 0][ld] = pa0.x;
            As2[nxt][lkh + 1][ld] = pa0.y;
            As2[nxt][lkh + 2][ld] = pa0.z;
            As2[nxt][lkh + 3][ld] = pa0.w;
            As2[nxt][lkh + 4][ld] = pa1.x;
            As2[nxt][lkh + 5][ld] = pa1.y;
            As2[nxt][lkh + 6][ld] = pa1.z;
            As2[nxt][lkh + 7][ld] = pa1.w;
            *(float4*)&Bs2[nxt][lrow    ][lcol] = pb0;
            *(float4*)&Bs2[nxt][lrow + 8][lcol] = pb1;
        }
        __syncthreads();
    }

    float* Crow = O + (size_t)b * D_ * N1_ + (size_t)(d0 + tm8) * N1_ + n1_0 + tn8;
    #pragma unroll
    for (int i = 0; i < 8; i++) {
        unsigned long long* cp = (unsigned long long*)(Crow + (size_t)i * N1_);
        cp[0] = acc[i][0]; cp[1] = acc[i][1]; cp[2] = acc[i][2]; cp[3] = acc[i][3];
    }
}

// ---------------------------------------------------------------------------
// Launch: scores -> attn region of d_out, softmax in place, then GEMM2.
// Graph-capturable: 3 plain launches on the legacy stream, no allocs/syncs.
// ---------------------------------------------------------------------------
extern "C" void kernel_launch(void* const* d_in, const int* in_sizes, int n_in,
                              void* d_out, int out_size)
{
    (void)in_sizes; (void)n_in; (void)out_size;
    const float* RI1 = (const float*)d_in[0];   // [B][C][N1]
    const float* RI2 = (const float*)d_in[1];   // [B][C][N2]
    const float* RE2 = (const float*)d_in[2];   // [B][D][N2]

    float* out   = (float*)d_out;
    float* embed = out;                                  // [B][D][N1]
    float* attn  = out + (size_t)B_ * D_ * N1_;          // [B][N2][N1]

    dim3 g1(N1_ / TILE, N2_ / TILE, B_);
    gemm1_kernel<<<g1, 256>>>(RI1, RI2, attn);

    softmax_kernel<<<(B_ * N1_) / 256, 256>>>(attn);

    dim3 g2(N1_ / TILE, D_ / TILE, B_);
    gemm2_kernel<<<g2, 256>>>(RE2, attn, embed);
}

// round 4
// speedup vs baseline: 1.8047x; 1.6838x over previous
#include <cuda_runtime.h>
#include <cstdint>
#include <cfloat>

#define B_   16
#define C_   512
#define D_   512
#define N1_  2048
#define N2_  2048

// ---------------------------------------------------------------------------
// scratch (__device__ globals: allocation-free)
// ---------------------------------------------------------------------------
__device__ float g_ri1t_hi[16 * 2048 * 512];
__device__ float g_ri1t_lo[16 * 2048 * 512];
__device__ float g_ri2t_hi[16 * 2048 * 512];
__device__ float g_ri2t_lo[16 * 2048 * 512];
__device__ float g_re2_hi [16 * 512 * 2048];
__device__ float g_re2_lo [16 * 512 * 2048];
__device__ float g_bt     [16 * 2048 * 2048];   // attention^T, tf32 single

// ---------------------------------------------------------------------------
// helpers
// ---------------------------------------------------------------------------
__device__ __forceinline__ uint32_t smem_u32(const void* p) {
    uint32_t a;
    asm("{ .reg .u64 t; cvta.to.shared.u64 t, %1; cvt.u32.u64 %0, t; }" : "=r"(a) : "l"(p));
    return a;
}
__device__ __forceinline__ void cpasync16(uint32_t dst, const void* src) {
    asm volatile("cp.async.cg.shared.global [%0], [%1], 16;" :: "r"(dst), "l"(src));
}
__device__ __forceinline__ void cp_commit() {
    asm volatile("cp.async.commit_group;" ::: "memory");
}
__device__ __forceinline__ void ldsm4(uint32_t* r, uint32_t addr) {
    asm volatile("ldmatrix.sync.aligned.m8n8.x4.shared.b16 {%0,%1,%2,%3}, [%4];"
                 : "=r"(r[0]), "=r"(r[1]), "=r"(r[2]), "=r"(r[3]) : "r"(addr));
}
__device__ __forceinline__ void mma8(float* d, const uint32_t* a, uint32_t b0, uint32_t b1) {
    asm volatile("mma.sync.aligned.m16n8k8.row.col.f32.tf32.tf32.f32 "
                 "{%0,%1,%2,%3}, {%4,%5,%6,%7}, {%8,%9}, {%0,%1,%2,%3};"
                 : "+f"(d[0]), "+f"(d[1]), "+f"(d[2]), "+f"(d[3])
                 : "r"(a[0]), "r"(a[1]), "r"(a[2]), "r"(a[3]), "r"(b0), "r"(b1));
}
__device__ __forceinline__ void tf32split(float x, float& h, float& l) {
    uint32_t hb, lb;
    asm("cvt.rna.tf32.f32 %0, %1;" : "=r"(hb) : "f"(x));
    h = __uint_as_float(hb);
    float r = x - h;
    asm("cvt.rna.tf32.f32 %0, %1;" : "=r"(lb) : "f"(r));
    l = __uint_as_float(lb);
}

// ---------------------------------------------------------------------------
// transpose + split: X[b][C][N] -> Thi/Tlo[b][N][C]
// ---------------------------------------------------------------------------
__global__ void tsplit_kernel(const float* __restrict__ X,
                              float* __restrict__ Thi, float* __restrict__ Tlo)
{
    __shared__ float tile[32][33];
    const int b = blockIdx.z;
    const int n0 = blockIdx.x * 32, c0 = blockIdx.y * 32;
    const int tx = threadIdx.x, ty = threadIdx.y;

    const size_t ib = (size_t)b * C_ * N1_;
    #pragma unroll
    for (int i = ty; i < 32; i += 8)
        tile[i][tx] = X[ib + (size_t)(c0 + i) * N1_ + n0 + tx];
    __syncthreads();

    const size_t ob = (size_t)b * N1_ * C_;
    #pragma unroll
    for (int i = ty; i < 32; i += 8) {
        float v = tile[tx][i];
        float h, l; tf32split(v, h, l);
        size_t o = ob + (size_t)(n0 + i) * C_ + c0 + tx;
        Thi[o] = h; Tlo[o] = l;
    }
}

// elementwise split (RE2)
__global__ void esplit_kernel(const float4* __restrict__ src,
                              float4* __restrict__ hi, float4* __restrict__ lo)
{
    const int i = blockIdx.x * blockDim.x + threadIdx.x;
    float4 v = src[i];
    float4 h, l;
    tf32split(v.x, h.x, l.x); tf32split(v.y, h.y, l.y);
    tf32split(v.z, h.z, l.z); tf32split(v.w, h.w, l.w);
    hi[i] = h; lo[i] = l;
}

// ---------------------------------------------------------------------------
// tf32-split GEMM via mma.sync.
// Out[b*aRows + m][n] (n-stride 2048) = sum_k A[row][k] * B[row][k]
// A: 2 versions (hi, lo); B: BV versions. All K-major, K = template.
// Block 128(M) x 256(N), 8 warps, warptile 64x64, k-stage 32, double buffer.
// ---------------------------------------------------------------------------
template<int BV, int K>
__global__ __launch_bounds__(256)
void gemm_mma(const float* __restrict__ Ahi, const float* __restrict__ Alo,
              const float* __restrict__ Bhi, const float* __restrict__ Blo,
              float* __restrict__ Out, int aRows)
{
    extern __shared__ __align__(128) char smem[];
    constexpr int A_SZ  = 128 * 128;              // 16KB per version
    constexpr int B_SZ  = 256 * 128;              // 32KB per version
    constexpr int STAGE = 2 * A_SZ + BV * B_SZ;
    constexpr int NS    = K / 32;

    const int t   = threadIdx.x;
    const int l   = t & 31;
    const int wid = t >> 5;
    const int wm  = wid >> 2;      // 0..1
    const int wn  = wid & 3;       // 0..3
    const uint32_t sb = smem_u32(smem);

    const int b = blockIdx.z;
    const size_t aRow0 = (size_t)b * aRows + blockIdx.y * 128;
    const size_t bRow0 = (size_t)b * 2048  + blockIdx.x * 256;

    // ldmatrix per-thread row bases
    uint32_t aBase[4], bBase[4];
    {
        int ra = wm * 64 + (l & 7) + ((l >> 3) & 1) * 8;
        #pragma unroll
        for (int mf = 0; mf < 4; mf++) aBase[mf] = sb + (uint32_t)(ra + mf * 16) * 128;
        int rb = wn * 64 + (l & 7) + ((l >> 4) & 1) * 8;
        #pragma unroll
        for (int p = 0; p < 4; p++)  bBase[p]  = sb + 2 * A_SZ + (uint32_t)(rb + p * 16) * 128;
    }
    const int aColBit = (l >> 4) & 1;
    const int bColBit = (l >> 3) & 1;
    const int r7 = l & 7;

    float acc[4][8][4];
    #pragma unroll
    for (int i = 0; i < 4; i++)
        #pragma unroll
        for (int j = 0; j < 8; j++)
            #pragma unroll
            for (int q = 0; q < 4; q++) acc[i][j][q] = 0.f;

    auto load_stage = [&](int st, int k0) {
        uint32_t base = sb + (uint32_t)st * STAGE;
        const float* asrc[2] = {Ahi, Alo};
        #pragma unroll
        for (int v = 0; v < 2; v++) {
            #pragma unroll
            for (int j = 0; j < 4; j++) {
                int idx = j * 256 + t;
                int row = idx >> 3, u = idx & 7;
                const float* g = asrc[v] + (aRow0 + row) * (size_t)K + k0 + u * 4;
                cpasync16(base + v * A_SZ + (uint32_t)row * 128 + (uint32_t)((u ^ (row & 7)) << 4), g);
            }
        }
        const float* bsrc[2] = {Bhi, Blo};
        #pragma unroll
        for (int v = 0; v < BV; v++) {
            #pragma unroll
            for (int j = 0; j < 8; j++) {
                int idx = j * 256 + t;
                int row = idx >> 3, u = idx & 7;
                const float* g = bsrc[v] + (bRow0 + row) * (size_t)K + k0 + u * 4;
                cpasync16(base + 2 * A_SZ + v * B_SZ + (uint32_t)row * 128 + (uint32_t)((u ^ (row & 7)) << 4), g);
            }
        }
    };

    load_stage(0, 0);  cp_commit();
    load_stage(1, 32); cp_commit();

    for (int c = 0; c < NS; c++) {
        asm volatile("cp.async.wait_group 1;" ::: "memory");
        __syncthreads();
        const uint32_t stb = (uint32_t)((c & 1) * STAGE);

        #pragma unroll
        for (int s = 0; s < 4; s++) {
            const uint32_t aswz = (uint32_t)(((2 * s + aColBit) ^ r7) << 4);
            const uint32_t bswz = (uint32_t)(((2 * s + bColBit) ^ r7) << 4);

            uint32_t ah[4][4], al[4][4];
            #pragma unroll
            for (int mf = 0; mf < 4; mf++) {
                ldsm4(ah[mf], aBase[mf] + stb + aswz);
                ldsm4(al[mf], aBase[mf] + stb + A_SZ + aswz);
            }
            #pragma unroll
            for (int p = 0; p < 4; p++) {
                uint32_t bh[4];
                ldsm4(bh, bBase[p] + stb + bswz);
                if (BV == 2) {
                    uint32_t bl[4];
                    ldsm4(bl, bBase[p] + stb + B_SZ + bswz);
                    #pragma unroll
                    for (int mf = 0; mf < 4; mf++) {
                        mma8(acc[mf][2 * p],     ah[mf], bh[0], bh[1]);
                        mma8(acc[mf][2 * p],     ah[mf], bl[0], bl[1]);
                        mma8(acc[mf][2 * p],     al[mf], bh[0], bh[1]);
                        mma8(acc[mf][2 * p + 1], ah[mf], bh[2], bh[3]);
                        mma8(acc[mf][2 * p + 1], ah[mf], bl[2], bl[3]);
                        mma8(acc[mf][2 * p + 1], al[mf], bh[2], bh[3]);
                    }
                } else {
                    #pragma unroll
                    for (int mf = 0; mf < 4; mf++) {
                        mma8(acc[mf][2 * p],     ah[mf], bh[0], bh[1]);
                        mma8(acc[mf][2 * p],     al[mf], bh[0], bh[1]);
                        mma8(acc[mf][2 * p + 1], ah[mf], bh[2], bh[3]);
                        mma8(acc[mf][2 * p + 1], al[mf], bh[2], bh[3]);
                    }
                }
            }
        }
        __syncthreads();
        if (c + 2 < NS) load_stage(c & 1, (c + 2) * 32);
        cp_commit();
    }

    // epilogue
    float* obase = Out + ((size_t)b * aRows + blockIdx.y * 128 + wm * 64) * 2048
                       + blockIdx.x * 256 + wn * 64;
    const int rr = l >> 2, cc = (l & 3) * 2;
    #pragma unroll
    for (int mf = 0; mf < 4; mf++) {
        #pragma unroll
        for (int nf = 0; nf < 8; nf++) {
            int r = mf * 16 + rr;
            int c = nf * 8 + cc;
            *(float2*)(obase + (size_t)r * 2048 + c)       = make_float2(acc[mf][nf][0], acc[mf][nf][1]);
            *(float2*)(obase + (size_t)(r + 8) * 2048 + c) = make_float2(acc[mf][nf][2], acc[mf][nf][3]);
        }
    }
}

// ---------------------------------------------------------------------------
// Softmax over n2 per (b,n1) column, in place on S; also writes tf32
// transposed copy Bt[b][n1][n2] (coalesced via 32x32 smem tiles).
// block (32,8), grid (N1/32, B)
// ---------------------------------------------------------------------------
__global__ void softmax_kernel(float* __restrict__ S, float* __restrict__ Bt)
{
    __shared__ float red_m[8][32], red_s[8][32];
    __shared__ float fin_m[32], fin_s[32];
    __shared__ float tile[32][33];

    const int x = threadIdx.x, y = threadIdx.y;
    const int b = blockIdx.y;
    const int n1b = blockIdx.x * 32;
    float* Sb = S + (size_t)b * N2_ * N1_ + n1b + x;

    float m = -FLT_MAX, s = 0.f;
    for (int n2 = y; n2 < N2_; n2 += 8) {
        float v = Sb[(size_t)n2 * N1_];
        float mn = fmaxf(m, v);
        s = s * __expf(m - mn) + __expf(v - mn);
        m = mn;
    }
    red_m[y][x] = m; red_s[y][x] = s;
    __syncthreads();
    if (y == 0) {
        float M = red_m[0][x], SS = red_s[0][x];
        #pragma unroll
        for (int j = 1; j < 8; j++) {
            float mj = red_m[j][x], sj = red_s[j][x];
            float mn = fmaxf(M, mj);
            SS = SS * __expf(M - mn) + sj * __expf(mj - mn);
            M = mn;
        }
        fin_m[x] = M; fin_s[x] = 1.0f / SS;
    }
    __syncthreads();
    const float M = fin_m[x], inv = fin_s[x];

    for (int t2 = 0; t2 < N2_; t2 += 32) {
        #pragma unroll
        for (int k = 0; k < 4; k++) {
            int r = t2 + y + 8 * k;
            float v = Sb[(size_t)r * N1_];
            float w = __expf(v - M) * inv;
            Sb[(size_t)r * N1_] = w;
            tile[y + 8 * k][x] = w;
        }
        __syncthreads();
        #pragma unroll
        for (int k = 0; k < 4; k++) {
            int ry = y + 8 * k;                       // local n1
            float w = tile[x][ry];
            uint32_t tf;
            asm("cvt.rna.tf32.f32 %0, %1;" : "=r"(tf) : "f"(w));
            Bt[((size_t)b * N1_ + n1b + ry) * N2_ + t2 + x] = __uint_as_float(tf);
        }
        __syncthreads();
    }
}

// ---------------------------------------------------------------------------
// launch
// ---------------------------------------------------------------------------
extern "C" void kernel_launch(void* const* d_in, const int* in_sizes, int n_in,
                              void* d_out, int out_size)
{
    (void)in_sizes; (void)n_in; (void)out_size;
    const float* RI1 = (const float*)d_in[0];   // [B][C][N1]
    const float* RI2 = (const float*)d_in[1];   // [B][C][N2]
    const float* RE2 = (const float*)d_in[2];   // [B][D][N2]

    float* out   = (float*)d_out;
    float* embed = out;                                  // [B][D][N1]
    float* attn  = out + (size_t)B_ * D_ * N1_;          // [B][N2][N1]

    void *ri1h, *ri1l, *ri2h, *ri2l, *re2h, *re2l, *bt;
    cudaGetSymbolAddress(&ri1h, g_ri1t_hi);
    cudaGetSymbolAddress(&ri1l, g_ri1t_lo);
    cudaGetSymbolAddress(&ri2h, g_ri2t_hi);
    cudaGetSymbolAddress(&ri2l, g_ri2t_lo);
    cudaGetSymbolAddress(&re2h, g_re2_hi);
    cudaGetSymbolAddress(&re2l, g_re2_lo);
    cudaGetSymbolAddress(&bt,   g_bt);

    constexpr int SMEM1 = 2 * (2 * 128 * 128 + 2 * 256 * 128);   // 196608
    constexpr int SMEM2 = 2 * (2 * 128 * 128 + 1 * 256 * 128);   // 131072
    cudaFuncSetAttribute(gemm_mma<2, 512>,
                         cudaFuncAttributeMaxDynamicSharedMemorySize, SMEM1);
    cudaFuncSetAttribute(gemm_mma<1, 2048>,
                         cudaFuncAttributeMaxDynamicSharedMemorySize, SMEM2);

    dim3 tb(32, 8);
    tsplit_kernel<<<dim3(N1_ / 32, C_ / 32, B_), tb>>>(RI1, (float*)ri1h, (float*)ri1l);
    tsplit_kernel<<<dim3(N2_ / 32, C_ / 32, B_), tb>>>(RI2, (float*)ri2h, (float*)ri2l);
    esplit_kernel<<<(B_ * D_ * N2_ / 4) / 256, 256>>>(
        (const float4*)RE2, (float4*)re2h, (float4*)re2l);

    // GEMM1: scores[b][n2][n1] = RI2T(hi/lo) x RI1T(hi/lo), K=512
    gemm_mma<2, 512><<<dim3(N1_ / 256, N2_ / 128, B_), 256, SMEM1>>>(
        (const float*)ri2h, (const float*)ri2l,
        (const float*)ri1h, (const float*)ri1l, attn, N2_);

    softmax_kernel<<<dim3(N1_ / 32, B_), tb>>>(attn, (float*)bt);

    // GEMM2: embed[b][d][n1] = RE2(hi/lo) x attnT(tf32), K=2048
    gemm_mma<1, 2048><<<dim3(N1_ / 256, D_ / 128, B_), 256, SMEM2>>>(
        (const float*)re2h, (const float*)re2l,
        (const float*)bt, nullptr, embed, D_);
}

// round 5
// speedup vs baseline: 2.6678x; 1.4782x over previous
#include <cuda_runtime.h>
#include <cuda_bf16.h>
#include <cstdint>
#include <cfloat>

#define B_   16
#define C_   512
#define D_   512
#define N1_  2048
#define N2_  2048

// ---------------------------------------------------------------------------
// scratch (__device__ globals: allocation-free), bf16 split operands
// ---------------------------------------------------------------------------
__device__ __align__(16) __nv_bfloat16 g_ri1t_hi[16 * 2048 * 512];
__device__ __align__(16) __nv_bfloat16 g_ri1t_lo[16 * 2048 * 512];
__device__ __align__(16) __nv_bfloat16 g_ri2t_hi[16 * 2048 * 512];
__device__ __align__(16) __nv_bfloat16 g_ri2t_lo[16 * 2048 * 512];
__device__ __align__(16) __nv_bfloat16 g_re2_hi [16 * 512 * 2048];
__device__ __align__(16) __nv_bfloat16 g_re2_lo [16 * 512 * 2048];
__device__ __align__(16) __nv_bfloat16 g_bt_hi  [16 * 2048 * 2048];
__device__ __align__(16) __nv_bfloat16 g_bt_lo  [16 * 2048 * 2048];

// ---------------------------------------------------------------------------
// helpers
// ---------------------------------------------------------------------------
__device__ __forceinline__ uint32_t smem_u32(const void* p) {
    uint32_t a;
    asm("{ .reg .u64 t; cvta.to.shared.u64 t, %1; cvt.u32.u64 %0, t; }" : "=r"(a) : "l"(p));
    return a;
}
__device__ __forceinline__ void cpasync16(uint32_t dst, const void* src) {
    asm volatile("cp.async.cg.shared.global [%0], [%1], 16;" :: "r"(dst), "l"(src));
}
__device__ __forceinline__ void cp_commit() {
    asm volatile("cp.async.commit_group;" ::: "memory");
}
__device__ __forceinline__ void ldsm4(uint32_t* r, uint32_t addr) {
    asm volatile("ldmatrix.sync.aligned.m8n8.x4.shared.b16 {%0,%1,%2,%3}, [%4];"
                 : "=r"(r[0]), "=r"(r[1]), "=r"(r[2]), "=r"(r[3]) : "r"(addr));
}
__device__ __forceinline__ void mma16(float* d, const uint32_t* a, uint32_t b0, uint32_t b1) {
    asm volatile("mma.sync.aligned.m16n8k16.row.col.f32.bf16.bf16.f32 "
                 "{%0,%1,%2,%3}, {%4,%5,%6,%7}, {%8,%9}, {%0,%1,%2,%3};"
                 : "+f"(d[0]), "+f"(d[1]), "+f"(d[2]), "+f"(d[3])
                 : "r"(a[0]), "r"(a[1]), "r"(a[2]), "r"(a[3]), "r"(b0), "r"(b1));
}
__device__ __forceinline__ void bsplit(float x, __nv_bfloat16& h, __nv_bfloat16& l) {
    h = __float2bfloat16(x);
    l = __float2bfloat16(x - __bfloat162float(h));
}

// ---------------------------------------------------------------------------
// transpose + bf16 split: X[b][C][N] -> Thi/Tlo[b][N][C]
// ---------------------------------------------------------------------------
__global__ void tsplit_kernel(const float* __restrict__ X,
                              __nv_bfloat16* __restrict__ Thi,
                              __nv_bfloat16* __restrict__ Tlo)
{
    __shared__ float tile[32][33];
    const int b = blockIdx.z;
    const int n0 = blockIdx.x * 32, c0 = blockIdx.y * 32;
    const int tx = threadIdx.x, ty = threadIdx.y;

    const size_t ib = (size_t)b * C_ * N1_;
    #pragma unroll
    for (int i = ty; i < 32; i += 8)
        tile[i][tx] = X[ib + (size_t)(c0 + i) * N1_ + n0 + tx];
    __syncthreads();

    const size_t ob = (size_t)b * N1_ * C_;
    #pragma unroll
    for (int i = ty; i < 32; i += 8) {
        float v = tile[tx][i];
        __nv_bfloat16 h, l; bsplit(v, h, l);
        size_t o = ob + (size_t)(n0 + i) * C_ + c0 + tx;
        Thi[o] = h; Tlo[o] = l;
    }
}

// elementwise bf16 split (RE2): K-major already
__global__ void esplit_kernel(const float4* __restrict__ src,
                              __nv_bfloat16* __restrict__ hi,
                              __nv_bfloat16* __restrict__ lo)
{
    const int i = blockIdx.x * blockDim.x + threadIdx.x;
    float4 v = src[i];
    __nv_bfloat16 h0, l0, h1, l1, h2, l2, h3, l3;
    bsplit(v.x, h0, l0); bsplit(v.y, h1, l1);
    bsplit(v.z, h2, l2); bsplit(v.w, h3, l3);
    __nv_bfloat162* H = (__nv_bfloat162*)(hi + (size_t)i * 4);
    __nv_bfloat162* L = (__nv_bfloat162*)(lo + (size_t)i * 4);
    H[0] = __nv_bfloat162(h0, h1); H[1] = __nv_bfloat162(h2, h3);
    L[0] = __nv_bfloat162(l0, l1); L[1] = __nv_bfloat162(l2, l3);
}

// ---------------------------------------------------------------------------
// bf16-split GEMM via mma.sync m16n8k16.
// Out[b*aRows + m][n] (n-stride 2048) = sum_k A[row][k] * B[row][k]
// with A ~ Ahi+Alo, B ~ Bhi+Blo, 3 products (hh + hl + lh).
// Block 128(M) x 256(N), 8 warps, warptile 64x64, k-stage 64, double buffer.
// ---------------------------------------------------------------------------
template<int K>
__global__ __launch_bounds__(256)
void gemm_mma(const __nv_bfloat16* __restrict__ Ahi, const __nv_bfloat16* __restrict__ Alo,
              const __nv_bfloat16* __restrict__ Bhi, const __nv_bfloat16* __restrict__ Blo,
              float* __restrict__ Out, int aRows)
{
    extern __shared__ __align__(128) char smem[];
    constexpr int A_SZ  = 128 * 128;              // bytes per A version (128 rows x 128B)
    constexpr int B_SZ  = 256 * 128;              // bytes per B version
    constexpr int STAGE = 2 * A_SZ + 2 * B_SZ;    // 98304
    constexpr int NS    = K / 64;                 // k-chunk = 64 bf16 = 128B row

    const int t   = threadIdx.x;
    const int l   = t & 31;
    const int wid = t >> 5;
    const int wm  = wid >> 2;      // 0..1
    const int wn  = wid & 3;       // 0..3
    const uint32_t sb = smem_u32(smem);

    const int b = blockIdx.z;
    const size_t aRow0 = (size_t)b * aRows + blockIdx.y * 128;
    const size_t bRow0 = (size_t)b * 2048  + blockIdx.x * 256;

    // ldmatrix per-thread row bases
    uint32_t aBase[4], bBase[4];
    {
        int ra = wm * 64 + (l & 7) + ((l >> 3) & 1) * 8;
        #pragma unroll
        for (int mf = 0; mf < 4; mf++) aBase[mf] = sb + (uint32_t)(ra + mf * 16) * 128;
        int rb = wn * 64 + (l & 7) + ((l >> 4) & 1) * 8;
        #pragma unroll
        for (int p = 0; p < 4; p++)  bBase[p]  = sb + 2 * A_SZ + (uint32_t)(rb + p * 16) * 128;
    }
    const int aColBit = (l >> 4) & 1;   // k8-half selector for A
    const int bColBit = (l >> 3) & 1;   // k8-half selector for B
    const int r7 = l & 7;

    float acc[4][8][4];
    #pragma unroll
    for (int i = 0; i < 4; i++)
        #pragma unroll
        for (int j = 0; j < 8; j++)
            #pragma unroll
            for (int q = 0; q < 4; q++) acc[i][j][q] = 0.f;

    auto load_stage = [&](int st, int k0) {
        uint32_t base = sb + (uint32_t)st * STAGE;
        const __nv_bfloat16* asrc[2] = {Ahi, Alo};
        #pragma unroll
        for (int v = 0; v < 2; v++) {
            #pragma unroll
            for (int j = 0; j < 4; j++) {
                int idx = j * 256 + t;
                int row = idx >> 3, u = idx & 7;           // u = 16B unit (8 bf16)
                const __nv_bfloat16* g = asrc[v] + (aRow0 + row) * (size_t)K + k0 + u * 8;
                cpasync16(base + v * A_SZ + (uint32_t)row * 128 + (uint32_t)((u ^ (row & 7)) << 4), g);
            }
        }
        const __nv_bfloat16* bsrc[2] = {Bhi, Blo};
        #pragma unroll
        for (int v = 0; v < 2; v++) {
            #pragma unroll
            for (int j = 0; j < 8; j++) {
                int idx = j * 256 + t;
                int row = idx >> 3, u = idx & 7;
                const __nv_bfloat16* g = bsrc[v] + (bRow0 + row) * (size_t)K + k0 + u * 8;
                cpasync16(base + 2 * A_SZ + v * B_SZ + (uint32_t)row * 128 + (uint32_t)((u ^ (row & 7)) << 4), g);
            }
        }
    };

    load_stage(0, 0);  cp_commit();
    load_stage(1, 64); cp_commit();

    for (int c = 0; c < NS; c++) {
        asm volatile("cp.async.wait_group 1;" ::: "memory");
        __syncthreads();
        const uint32_t stb = (uint32_t)((c & 1) * STAGE);

        #pragma unroll
        for (int s = 0; s < 4; s++) {                      // k16 steps within k64
            const uint32_t aswz = (uint32_t)(((2 * s + aColBit) ^ r7) << 4);
            const uint32_t bswz = (uint32_t)(((2 * s + bColBit) ^ r7) << 4);

            uint32_t ah[4][4], al[4][4];
            #pragma unroll
            for (int mf = 0; mf < 4; mf++) {
                ldsm4(ah[mf], aBase[mf] + stb + aswz);
                ldsm4(al[mf], aBase[mf] + stb + A_SZ + aswz);
            }
            #pragma unroll
            for (int p = 0; p < 4; p++) {
                uint32_t bh[4], bl[4];
                ldsm4(bh, bBase[p] + stb + bswz);
                ldsm4(bl, bBase[p] + stb + B_SZ + bswz);
                #pragma unroll
                for (int mf = 0; mf < 4; mf++) {
                    mma16(acc[mf][2 * p],     ah[mf], bh[0], bh[1]);
                    mma16(acc[mf][2 * p],     ah[mf], bl[0], bl[1]);
                    mma16(acc[mf][2 * p],     al[mf], bh[0], bh[1]);
                    mma16(acc[mf][2 * p + 1], ah[mf], bh[2], bh[3]);
                    mma16(acc[mf][2 * p + 1], ah[mf], bl[2], bl[3]);
                    mma16(acc[mf][2 * p + 1], al[mf], bh[2], bh[3]);
                }
            }
        }
        __syncthreads();
        if (c + 2 < NS) load_stage(c & 1, (c + 2) * 64);
        cp_commit();
    }

    // epilogue
    float* obase = Out + ((size_t)b * aRows + blockIdx.y * 128 + wm * 64) * 2048
                       + blockIdx.x * 256 + wn * 64;
    const int rr = l >> 2, cc = (l & 3) * 2;
    #pragma unroll
    for (int mf = 0; mf < 4; mf++) {
        #pragma unroll
        for (int nf = 0; nf < 8; nf++) {
            int r = mf * 16 + rr;
            int c = nf * 8 + cc;
            *(float2*)(obase + (size_t)r * 2048 + c)       = make_float2(acc[mf][nf][0], acc[mf][nf][1]);
            *(float2*)(obase + (size_t)(r + 8) * 2048 + c) = make_float2(acc[mf][nf][2], acc[mf][nf][3]);
        }
    }
}

// ---------------------------------------------------------------------------
// Softmax over n2 per (b,n1) column, in place on S; also writes bf16 split
// transposed copies Bt{hi,lo}[b][n1][n2] (coalesced via 32x32 smem tiles).
// block (32,8), grid (N1/32, B)
// ---------------------------------------------------------------------------
__global__ void softmax_kernel(float* __restrict__ S,
                               __nv_bfloat16* __restrict__ BtHi,
                               __nv_bfloat16* __restrict__ BtLo)
{
    __shared__ float red_m[8][32], red_s[8][32];
    __shared__ float fin_m[32], fin_s[32];
    __shared__ float tile[32][33];

    const int x = threadIdx.x, y = threadIdx.y;
    const int b = blockIdx.y;
    const int n1b = blockIdx.x * 32;
    float* Sb = S + (size_t)b * N2_ * N1_ + n1b + x;

    float m = -FLT_MAX, s = 0.f;
    for (int n2 = y; n2 < N2_; n2 += 8) {
        float v = Sb[(size_t)n2 * N1_];
        float mn = fmaxf(m, v);
        s = s * __expf(m - mn) + __expf(v - mn);
        m = mn;
    }
    red_m[y][x] = m; red_s[y][x] = s;
    __syncthreads();
    if (y == 0) {
        float M = red_m[0][x], SS = red_s[0][x];
        #pragma unroll
        for (int j = 1; j < 8; j++) {
            float mj = red_m[j][x], sj = red_s[j][x];
            float mn = fmaxf(M, mj);
            SS = SS * __expf(M - mn) + sj * __expf(mj - mn);
            M = mn;
        }
        fin_m[x] = M; fin_s[x] = 1.0f / SS;
    }
    __syncthreads();
    const float M = fin_m[x], inv = fin_s[x];

    for (int t2 = 0; t2 < N2_; t2 += 32) {
        #pragma unroll
        for (int k = 0; k < 4; k++) {
            int r = t2 + y + 8 * k;
            float v = Sb[(size_t)r * N1_];
            float w = __expf(v - M) * inv;
            Sb[(size_t)r * N1_] = w;
            tile[y + 8 * k][x] = w;
        }
        __syncthreads();
        #pragma unroll
        for (int k = 0; k < 4; k++) {
            int ry = y + 8 * k;                       // local n1
            float w = tile[x][ry];
            __nv_bfloat16 h, l2; bsplit(w, h, l2);
            size_t o = ((size_t)b * N1_ + n1b + ry) * N2_ + t2 + x;
            BtHi[o] = h; BtLo[o] = l2;
        }
        __syncthreads();
    }
}

// ---------------------------------------------------------------------------
// launch
// ---------------------------------------------------------------------------
extern "C" void kernel_launch(void* const* d_in, const int* in_sizes, int n_in,
                              void* d_out, int out_size)
{
    (void)in_sizes; (void)n_in; (void)out_size;
    const float* RI1 = (const float*)d_in[0];   // [B][C][N1]
    const float* RI2 = (const float*)d_in[1];   // [B][C][N2]
    const float* RE2 = (const float*)d_in[2];   // [B][D][N2]

    float* out   = (float*)d_out;
    float* embed = out;                                  // [B][D][N1]
    float* attn  = out + (size_t)B_ * D_ * N1_;          // [B][N2][N1]

    void *ri1h, *ri1l, *ri2h, *ri2l, *re2h, *re2l, *bth, *btl;
    cudaGetSymbolAddress(&ri1h, g_ri1t_hi);
    cudaGetSymbolAddress(&ri1l, g_ri1t_lo);
    cudaGetSymbolAddress(&ri2h, g_ri2t_hi);
    cudaGetSymbolAddress(&ri2l, g_ri2t_lo);
    cudaGetSymbolAddress(&re2h, g_re2_hi);
    cudaGetSymbolAddress(&re2l, g_re2_lo);
    cudaGetSymbolAddress(&bth,  g_bt_hi);
    cudaGetSymbolAddress(&btl,  g_bt_lo);

    constexpr int SMEM = 2 * (2 * 128 * 128 + 2 * 256 * 128);   // 196608
    cudaFuncSetAttribute(gemm_mma<512>,
                         cudaFuncAttributeMaxDynamicSharedMemorySize, SMEM);
    cudaFuncSetAttribute(gemm_mma<2048>,
                         cudaFuncAttributeMaxDynamicSharedMemorySize, SMEM);

    dim3 tb(32, 8);
    tsplit_kernel<<<dim3(N1_ / 32, C_ / 32, B_), tb>>>(
        RI1, (__nv_bfloat16*)ri1h, (__nv_bfloat16*)ri1l);
    tsplit_kernel<<<dim3(N2_ / 32, C_ / 32, B_), tb>>>(
        RI2, (__nv_bfloat16*)ri2h, (__nv_bfloat16*)ri2l);
    esplit_kernel<<<(B_ * D_ * N2_ / 4) / 256, 256>>>(
        (const float4*)RE2, (__nv_bfloat16*)re2h, (__nv_bfloat16*)re2l);

    // GEMM1: scores[b][n2][n1] = RI2T x RI1T (bf16 split), K=512
    gemm_mma<512><<<dim3(N1_ / 256, N2_ / 128, B_), 256, SMEM>>>(
        (const __nv_bfloat16*)ri2h, (const __nv_bfloat16*)ri2l,
        (const __nv_bfloat16*)ri1h, (const __nv_bfloat16*)ri1l, attn, N2_);

    softmax_kernel<<<dim3(N1_ / 32, B_), tb>>>(
        attn, (__nv_bfloat16*)bth, (__nv_bfloat16*)btl);

    // GEMM2: embed[b][d][n1] = RE2 x attnT (bf16 split), K=2048
    gemm_mma<2048><<<dim3(N1_ / 256, D_ / 128, B_), 256, SMEM>>>(
        (const __nv_bfloat16*)re2h, (const __nv_bfloat16*)re2l,
        (const __nv_bfloat16*)bth,  (const __nv_bfloat16*)btl, embed, D_);
}

// round 6
// speedup vs baseline: 3.1108x; 1.1661x over previous
#include <cuda_runtime.h>
#include <cuda_fp16.h>
#include <cstdint>
#include <cfloat>

#define B_   16
#define C_   512
#define D_   512
#define N1_  2048
#define N2_  2048

// ---------------------------------------------------------------------------
// scratch (__device__ globals: allocation-free), fp16 split operands
// ---------------------------------------------------------------------------
__device__ __align__(16) __half g_ri1t_hi[16 * 2048 * 512];
__device__ __align__(16) __half g_ri1t_lo[16 * 2048 * 512];
__device__ __align__(16) __half g_ri2t_hi[16 * 2048 * 512];
__device__ __align__(16) __half g_ri2t_lo[16 * 2048 * 512];
__device__ __align__(16) __half g_re2_hi [16 * 512 * 2048];
__device__ __align__(16) __half g_re2_lo [16 * 512 * 2048];
__device__ __align__(16) __half g_bt     [16 * 2048 * 2048];   // attn^T fp16

// ---------------------------------------------------------------------------
// helpers
// ---------------------------------------------------------------------------
__device__ __forceinline__ uint32_t smem_u32(const void* p) {
    uint32_t a;
    asm("{ .reg .u64 t; cvta.to.shared.u64 t, %1; cvt.u32.u64 %0, t; }" : "=r"(a) : "l"(p));
    return a;
}
__device__ __forceinline__ void cpasync16(uint32_t dst, const void* src) {
    asm volatile("cp.async.cg.shared.global [%0], [%1], 16;" :: "r"(dst), "l"(src));
}
__device__ __forceinline__ void cp_commit() {
    asm volatile("cp.async.commit_group;" ::: "memory");
}
__device__ __forceinline__ void ldsm4(uint32_t* r, uint32_t addr) {
    asm volatile("ldmatrix.sync.aligned.m8n8.x4.shared.b16 {%0,%1,%2,%3}, [%4];"
                 : "=r"(r[0]), "=r"(r[1]), "=r"(r[2]), "=r"(r[3]) : "r"(addr));
}
__device__ __forceinline__ void mma16(float* d, const uint32_t* a, uint32_t b0, uint32_t b1) {
    asm volatile("mma.sync.aligned.m16n8k16.row.col.f32.f16.f16.f32 "
                 "{%0,%1,%2,%3}, {%4,%5,%6,%7}, {%8,%9}, {%0,%1,%2,%3};"
                 : "+f"(d[0]), "+f"(d[1]), "+f"(d[2]), "+f"(d[3])
                 : "r"(a[0]), "r"(a[1]), "r"(a[2]), "r"(a[3]), "r"(b0), "r"(b1));
}
__device__ __forceinline__ void hsplit(float x, __half& h, __half& l) {
    h = __float2half_rn(x);
    l = __float2half_rn(x - __half2float(h));
}

// ---------------------------------------------------------------------------
// transpose + fp16 split: X[b][C][N] -> Thi/Tlo[b][N][C]
// ---------------------------------------------------------------------------
__global__ void tsplit_kernel(const float* __restrict__ X,
                              __half* __restrict__ Thi, __half* __restrict__ Tlo)
{
    __shared__ float tile[32][33];
    const int b = blockIdx.z;
    const int n0 = blockIdx.x * 32, c0 = blockIdx.y * 32;
    const int tx = threadIdx.x, ty = threadIdx.y;

    const size_t ib = (size_t)b * C_ * N1_;
    #pragma unroll
    for (int i = ty; i < 32; i += 8)
        tile[i][tx] = X[ib + (size_t)(c0 + i) * N1_ + n0 + tx];
    __syncthreads();

    const size_t ob = (size_t)b * N1_ * C_;
    #pragma unroll
    for (int i = ty; i < 32; i += 8) {
        float v = tile[tx][i];
        __half h, l; hsplit(v, h, l);
        size_t o = ob + (size_t)(n0 + i) * C_ + c0 + tx;
        Thi[o] = h; Tlo[o] = l;
    }
}

// elementwise fp16 split (RE2): K-major already
__global__ void esplit_kernel(const float4* __restrict__ src,
                              __half* __restrict__ hi, __half* __restrict__ lo)
{
    const int i = blockIdx.x * blockDim.x + threadIdx.x;
    float4 v = src[i];
    __half h0, l0, h1, l1, h2, l2, h3, l3;
    hsplit(v.x, h0, l0); hsplit(v.y, h1, l1);
    hsplit(v.z, h2, l2); hsplit(v.w, h3, l3);
    __half2* H = (__half2*)(hi + (size_t)i * 4);
    __half2* L = (__half2*)(lo + (size_t)i * 4);
    H[0] = __half2(h0, h1); H[1] = __half2(h2, h3);
    L[0] = __half2(l0, l1); L[1] = __half2(l2, l3);
}

// ---------------------------------------------------------------------------
// fp16-split GEMM via mma.sync m16n8k16.
// Out[b*aRows + m][n] (n-stride 2048) = sum_k A[row][k] * B[row][k]
// A ~ Ahi+Alo always. BV=2: B ~ Bhi+Blo, 3 products (hh+hl+lh).
//                     BV=1: B single,    2 products (hB+lB).
// Block 128(M) x 256(N), 8 warps, warptile 64x64, k-chunk 64, STAGES buffers.
// ---------------------------------------------------------------------------
template<int K, int BV, int STAGES>
__global__ __launch_bounds__(256)
void gemm_mma(const __half* __restrict__ Ahi, const __half* __restrict__ Alo,
              const __half* __restrict__ Bhi, const __half* __restrict__ Blo,
              float* __restrict__ Out, int aRows)
{
    extern __shared__ __align__(128) char smem[];
    constexpr int A_SZ  = 128 * 128;              // bytes per A version
    constexpr int B_SZ  = 256 * 128;              // bytes per B version
    constexpr int STAGE = 2 * A_SZ + BV * B_SZ;
    constexpr int NS    = K / 64;                 // k-chunk = 64 fp16 = 128B row

    const int t   = threadIdx.x;
    const int l   = t & 31;
    const int wid = t >> 5;
    const int wm  = wid >> 2;      // 0..1
    const int wn  = wid & 3;       // 0..3
    const uint32_t sb = smem_u32(smem);

    const int b = blockIdx.z;
    const size_t aRow0 = (size_t)b * aRows + blockIdx.y * 128;
    const size_t bRow0 = (size_t)b * 2048  + blockIdx.x * 256;

    uint32_t aBase[4], bBase[4];
    {
        int ra = wm * 64 + (l & 7) + ((l >> 3) & 1) * 8;
        #pragma unroll
        for (int mf = 0; mf < 4; mf++) aBase[mf] = sb + (uint32_t)(ra + mf * 16) * 128;
        int rb = wn * 64 + (l & 7) + ((l >> 4) & 1) * 8;
        #pragma unroll
        for (int p = 0; p < 4; p++)  bBase[p]  = sb + 2 * A_SZ + (uint32_t)(rb + p * 16) * 128;
    }
    const int aColBit = (l >> 4) & 1;
    const int bColBit = (l >> 3) & 1;
    const int r7 = l & 7;

    float acc[4][8][4];
    #pragma unroll
    for (int i = 0; i < 4; i++)
        #pragma unroll
        for (int j = 0; j < 8; j++)
            #pragma unroll
            for (int q = 0; q < 4; q++) acc[i][j][q] = 0.f;

    auto load_stage = [&](int st, int k0) {
        uint32_t base = sb + (uint32_t)st * STAGE;
        const __half* asrc[2] = {Ahi, Alo};
        #pragma unroll
        for (int v = 0; v < 2; v++) {
            #pragma unroll
            for (int j = 0; j < 4; j++) {
                int idx = j * 256 + t;
                int row = idx >> 3, u = idx & 7;           // u = 16B unit (8 fp16)
                const __half* g = asrc[v] + (aRow0 + row) * (size_t)K + k0 + u * 8;
                cpasync16(base + v * A_SZ + (uint32_t)row * 128 + (uint32_t)((u ^ (row & 7)) << 4), g);
            }
        }
        const __half* bsrc[2] = {Bhi, Blo};
        #pragma unroll
        for (int v = 0; v < BV; v++) {
            #pragma unroll
            for (int j = 0; j < 8; j++) {
                int idx = j * 256 + t;
                int row = idx >> 3, u = idx & 7;
                const __half* g = bsrc[v] + (bRow0 + row) * (size_t)K + k0 + u * 8;
                cpasync16(base + 2 * A_SZ + v * B_SZ + (uint32_t)row * 128 + (uint32_t)((u ^ (row & 7)) << 4), g);
            }
        }
    };

    #pragma unroll
    for (int s = 0; s < STAGES; s++) {
        load_stage(s, s * 64);
        cp_commit();
    }

    int stageIdx = 0;
    for (int c = 0; c < NS; c++) {
        if (STAGES == 2) asm volatile("cp.async.wait_group 1;" ::: "memory");
        else             asm volatile("cp.async.wait_group 2;" ::: "memory");
        __syncthreads();
        const uint32_t stb = (uint32_t)(stageIdx * STAGE);

        #pragma unroll
        for (int s = 0; s < 4; s++) {                      // k16 steps within k64
            const uint32_t aswz = (uint32_t)(((2 * s + aColBit) ^ r7) << 4);
            const uint32_t bswz = (uint32_t)(((2 * s + bColBit) ^ r7) << 4);

            uint32_t ah[4][4], al[4][4];
            #pragma unroll
            for (int mf = 0; mf < 4; mf++) {
                ldsm4(ah[mf], aBase[mf] + stb + aswz);
                ldsm4(al[mf], aBase[mf] + stb + A_SZ + aswz);
            }
            #pragma unroll
            for (int p = 0; p < 4; p++) {
                uint32_t bh[4];
                ldsm4(bh, bBase[p] + stb + bswz);
                if (BV == 2) {
                    uint32_t bl[4];
                    ldsm4(bl, bBase[p] + stb + B_SZ + bswz);
                    #pragma unroll
                    for (int mf = 0; mf < 4; mf++) {
                        mma16(acc[mf][2 * p],     ah[mf], bh[0], bh[1]);
                        mma16(acc[mf][2 * p],     ah[mf], bl[0], bl[1]);
                        mma16(acc[mf][2 * p],     al[mf], bh[0], bh[1]);
                        mma16(acc[mf][2 * p + 1], ah[mf], bh[2], bh[3]);
                        mma16(acc[mf][2 * p + 1], ah[mf], bl[2], bl[3]);
                        mma16(acc[mf][2 * p + 1], al[mf], bh[2], bh[3]);
                    }
                } else {
                    #pragma unroll
                    for (int mf = 0; mf < 4; mf++) {
                        mma16(acc[mf][2 * p],     ah[mf], bh[0], bh[1]);
                        mma16(acc[mf][2 * p],     al[mf], bh[0], bh[1]);
                        mma16(acc[mf][2 * p + 1], ah[mf], bh[2], bh[3]);
                        mma16(acc[mf][2 * p + 1], al[mf], bh[2], bh[3]);
                    }
                }
            }
        }
        __syncthreads();
        if (c + STAGES < NS) load_stage(stageIdx, (c + STAGES) * 64);
        cp_commit();
        stageIdx = (stageIdx + 1 == STAGES) ? 0 : stageIdx + 1;
    }

    // epilogue
    float* obase = Out + ((size_t)b * aRows + blockIdx.y * 128 + wm * 64) * 2048
                       + blockIdx.x * 256 + wn * 64;
    const int rr = l >> 2, cc = (l & 3) * 2;
    #pragma unroll
    for (int mf = 0; mf < 4; mf++) {
        #pragma unroll
        for (int nf = 0; nf < 8; nf++) {
            int r = mf * 16 + rr;
            int c = nf * 8 + cc;
            *(float2*)(obase + (size_t)r * 2048 + c)       = make_float2(acc[mf][nf][0], acc[mf][nf][1]);
            *(float2*)(obase + (size_t)(r + 8) * 2048 + c) = make_float2(acc[mf][nf][2], acc[mf][nf][3]);
        }
    }
}

// ---------------------------------------------------------------------------
// Softmax over n2 per (b,n1) column, in place on S; also writes fp16
// transposed copy Bt[b][n1][n2] (coalesced via 32x32 smem tiles).
// block (32,8), grid (N1/32, B)
// ---------------------------------------------------------------------------
__global__ void softmax_kernel(float* __restrict__ S, __half* __restrict__ Bt)
{
    __shared__ float red_m[8][32], red_s[8][32];
    __shared__ float fin_m[32], fin_s[32];
    __shared__ float tile[32][33];

    const int x = threadIdx.x, y = threadIdx.y;
    const int b = blockIdx.y;
    const int n1b = blockIdx.x * 32;
    float* Sb = S + (size_t)b * N2_ * N1_ + n1b + x;

    float m = -FLT_MAX, s = 0.f;
    for (int n2 = y; n2 < N2_; n2 += 8) {
        float v = Sb[(size_t)n2 * N1_];
        float mn = fmaxf(m, v);
        s = s * __expf(m - mn) + __expf(v - mn);
        m = mn;
    }
    red_m[y][x] = m; red_s[y][x] = s;
    __syncthreads();
    if (y == 0) {
        float M = red_m[0][x], SS = red_s[0][x];
        #pragma unroll
        for (int j = 1; j < 8; j++) {
            float mj = red_m[j][x], sj = red_s[j][x];
            float mn = fmaxf(M, mj);
            SS = SS * __expf(M - mn) + sj * __expf(mj - mn);
            M = mn;
        }
        fin_m[x] = M; fin_s[x] = 1.0f / SS;
    }
    __syncthreads();
    const float M = fin_m[x], inv = fin_s[x];

    for (int t2 = 0; t2 < N2_; t2 += 32) {
        #pragma unroll
        for (int k = 0; k < 4; k++) {
            int r = t2 + y + 8 * k;
            float v = Sb[(size_t)r * N1_];
            float w = __expf(v - M) * inv;
            Sb[(size_t)r * N1_] = w;
            tile[y + 8 * k][x] = w;
        }
        __syncthreads();
        #pragma unroll
        for (int k = 0; k < 4; k++) {
            int ry = y + 8 * k;                       // local n1
            float w = tile[x][ry];
            Bt[((size_t)b * N1_ + n1b + ry) * N2_ + t2 + x] = __float2half_rn(w);
        }
        __syncthreads();
    }
}

// ---------------------------------------------------------------------------
// launch
// ---------------------------------------------------------------------------
extern "C" void kernel_launch(void* const* d_in, const int* in_sizes, int n_in,
                              void* d_out, int out_size)
{
    (void)in_sizes; (void)n_in; (void)out_size;
    const float* RI1 = (const float*)d_in[0];   // [B][C][N1]
    const float* RI2 = (const float*)d_in[1];   // [B][C][N2]
    const float* RE2 = (const float*)d_in[2];   // [B][D][N2]

    float* out   = (float*)d_out;
    float* embed = out;                                  // [B][D][N1]
    float* attn  = out + (size_t)B_ * D_ * N1_;          // [B][N2][N1]

    void *ri1h, *ri1l, *ri2h, *ri2l, *re2h, *re2l, *bt;
    cudaGetSymbolAddress(&ri1h, g_ri1t_hi);
    cudaGetSymbolAddress(&ri1l, g_ri1t_lo);
    cudaGetSymbolAddress(&ri2h, g_ri2t_hi);
    cudaGetSymbolAddress(&ri2l, g_ri2t_lo);
    cudaGetSymbolAddress(&re2h, g_re2_hi);
    cudaGetSymbolAddress(&re2l, g_re2_lo);
    cudaGetSymbolAddress(&bt,   g_bt);

    constexpr int SMEM1 = 2 * (2 * 128 * 128 + 2 * 256 * 128);   // 196608
    constexpr int SMEM2 = 3 * (2 * 128 * 128 + 1 * 256 * 128);   // 196608
    cudaFuncSetAttribute((const void*)gemm_mma<512, 2, 2>,
                         cudaFuncAttributeMaxDynamicSharedMemorySize, SMEM1);
    cudaFuncSetAttribute((const void*)gemm_mma<2048, 1, 3>,
                         cudaFuncAttributeMaxDynamicSharedMemorySize, SMEM2);

    dim3 tb(32, 8);
    tsplit_kernel<<<dim3(N1_ / 32, C_ / 32, B_), tb>>>(
        RI1, (__half*)ri1h, (__half*)ri1l);
    tsplit_kernel<<<dim3(N2_ / 32, C_ / 32, B_), tb>>>(
        RI2, (__half*)ri2h, (__half*)ri2l);
    esplit_kernel<<<(B_ * D_ * N2_ / 4) / 256, 256>>>(
        (const float4*)RE2, (__half*)re2h, (__half*)re2l);

    // GEMM1: scores[b][n2][n1] = RI2T x RI1T (fp16 split, 3 products), K=512
    gemm_mma<512, 2, 2><<<dim3(N1_ / 256, N2_ / 128, B_), 256, SMEM1>>>(
        (const __half*)ri2h, (const __half*)ri2l,
        (const __half*)ri1h, (const __half*)ri1l, attn, N2_);

    softmax_kernel<<<dim3(N1_ / 32, B_), tb>>>(attn, (__half*)bt);

    // GEMM2: embed[b][d][n1] = RE2(split) x attnT(fp16), 2 products, K=2048
    gemm_mma<2048, 1, 3><<<dim3(N1_ / 256, D_ / 128, B_), 256, SMEM2>>>(
        (const __half*)re2h, (const __half*)re2l,
        (const __half*)bt, nullptr, embed, D_);
}

// round 7
// speedup vs baseline: 3.5906x; 1.1542x over previous
#include <cuda_runtime.h>
#include <cuda_fp16.h>
#include <cstdint>
#include <cfloat>

#define B_   16
#define C_   512
#define D_   512
#define N1_  2048
#define N2_  2048

// ---------------------------------------------------------------------------
// scratch (__device__ globals: allocation-free), fp16 operands
// ---------------------------------------------------------------------------
__device__ __align__(16) __half g_ri1t_hi[16 * 2048 * 512];
__device__ __align__(16) __half g_ri1t_lo[16 * 2048 * 512];
__device__ __align__(16) __half g_ri2t_hi[16 * 2048 * 512];
__device__ __align__(16) __half g_ri2t_lo[16 * 2048 * 512];
__device__ __align__(16) __half g_re2    [16 * 512 * 2048];
__device__ __align__(16) __half g_bt     [16 * 2048 * 2048];   // attn^T fp16

// ---------------------------------------------------------------------------
// helpers
// ---------------------------------------------------------------------------
__device__ __forceinline__ uint32_t smem_u32(const void* p) {
    uint32_t a;
    asm("{ .reg .u64 t; cvta.to.shared.u64 t, %1; cvt.u32.u64 %0, t; }" : "=r"(a) : "l"(p));
    return a;
}
__device__ __forceinline__ void cpasync16(uint32_t dst, const void* src) {
    asm volatile("cp.async.cg.shared.global [%0], [%1], 16;" :: "r"(dst), "l"(src));
}
__device__ __forceinline__ void cp_commit() {
    asm volatile("cp.async.commit_group;" ::: "memory");
}
__device__ __forceinline__ void ldsm4(uint32_t* r, uint32_t addr) {
    asm volatile("ldmatrix.sync.aligned.m8n8.x4.shared.b16 {%0,%1,%2,%3}, [%4];"
                 : "=r"(r[0]), "=r"(r[1]), "=r"(r[2]), "=r"(r[3]) : "r"(addr));
}
__device__ __forceinline__ void mma16(float* d, const uint32_t* a, uint32_t b0, uint32_t b1) {
    asm volatile("mma.sync.aligned.m16n8k16.row.col.f32.f16.f16.f32 "
                 "{%0,%1,%2,%3}, {%4,%5,%6,%7}, {%8,%9}, {%0,%1,%2,%3};"
                 : "+f"(d[0]), "+f"(d[1]), "+f"(d[2]), "+f"(d[3])
                 : "r"(a[0]), "r"(a[1]), "r"(a[2]), "r"(a[3]), "r"(b0), "r"(b1));
}
__device__ __forceinline__ void hsplit(float x, __half& h, __half& l) {
    h = __float2half_rn(x);
    l = __float2half_rn(x - __half2float(h));
}

// ---------------------------------------------------------------------------
// transpose + fp16 split: X[b][C][N] -> Thi/Tlo[b][N][C]
// ---------------------------------------------------------------------------
__global__ void tsplit_kernel(const float* __restrict__ X,
                              __half* __restrict__ Thi, __half* __restrict__ Tlo)
{
    __shared__ float tile[32][33];
    const int b = blockIdx.z;
    const int n0 = blockIdx.x * 32, c0 = blockIdx.y * 32;
    const int tx = threadIdx.x, ty = threadIdx.y;

    const size_t ib = (size_t)b * C_ * N1_;
    #pragma unroll
    for (int i = ty; i < 32; i += 8)
        tile[i][tx] = X[ib + (size_t)(c0 + i) * N1_ + n0 + tx];
    __syncthreads();

    const size_t ob = (size_t)b * N1_ * C_;
    #pragma unroll
    for (int i = ty; i < 32; i += 8) {
        float v = tile[tx][i];
        __half h, l; hsplit(v, h, l);
        size_t o = ob + (size_t)(n0 + i) * C_ + c0 + tx;
        Thi[o] = h; Tlo[o] = l;
    }
}

// plain fp16 convert (RE2): K-major already
__global__ void hconv_kernel(const float4* __restrict__ src,
                             __half* __restrict__ dst)
{
    const int i = blockIdx.x * blockDim.x + threadIdx.x;
    float4 v = src[i];
    __half2* D = (__half2*)(dst + (size_t)i * 4);
    D[0] = __half2(__float2half_rn(v.x), __float2half_rn(v.y));
    D[1] = __half2(__float2half_rn(v.z), __float2half_rn(v.w));
}

// ---------------------------------------------------------------------------
// fp16 GEMM via mma.sync m16n8k16.
// Out[b*aRows + m][n] (n-stride 2048) = sum_k A[row][k] * B[row][k]
// AV/BV = number of split versions per operand.
//   AV2,BV2 -> 3 products (hh+hl+lh);  AV1,BV1 -> 1 product.
// Block 128(M) x 256(N), 8 warps, warptile 64x64, k-chunk 64, STAGES buffers.
// ---------------------------------------------------------------------------
template<int K, int AV, int BV, int STAGES>
__global__ __launch_bounds__(256)
void gemm_mma(const __half* __restrict__ Ahi, const __half* __restrict__ Alo,
              const __half* __restrict__ Bhi, const __half* __restrict__ Blo,
              float* __restrict__ Out, int aRows)
{
    extern __shared__ __align__(128) char smem[];
    constexpr int A_SZ  = 128 * 128;              // bytes per A version
    constexpr int B_SZ  = 256 * 128;              // bytes per B version
    constexpr int STAGE = AV * A_SZ + BV * B_SZ;
    constexpr int NS    = K / 64;                 // k-chunk = 64 fp16 = 128B row

    const int t   = threadIdx.x;
    const int l   = t & 31;
    const int wid = t >> 5;
    const int wm  = wid >> 2;      // 0..1
    const int wn  = wid & 3;       // 0..3
    const uint32_t sb = smem_u32(smem);

    const int b = blockIdx.z;
    const size_t aRow0 = (size_t)b * aRows + blockIdx.y * 128;
    const size_t bRow0 = (size_t)b * 2048  + blockIdx.x * 256;

    uint32_t aBase[4], bBase[4];
    {
        int ra = wm * 64 + (l & 7) + ((l >> 3) & 1) * 8;
        #pragma unroll
        for (int mf = 0; mf < 4; mf++) aBase[mf] = sb + (uint32_t)(ra + mf * 16) * 128;
        int rb = wn * 64 + (l & 7) + ((l >> 4) & 1) * 8;
        #pragma unroll
        for (int p = 0; p < 4; p++)  bBase[p]  = sb + AV * A_SZ + (uint32_t)(rb + p * 16) * 128;
    }
    const int aColBit = (l >> 4) & 1;
    const int bColBit = (l >> 3) & 1;
    const int r7 = l & 7;

    float acc[4][8][4];
    #pragma unroll
    for (int i = 0; i < 4; i++)
        #pragma unroll
        for (int j = 0; j < 8; j++)
            #pragma unroll
            for (int q = 0; q < 4; q++) acc[i][j][q] = 0.f;

    auto load_stage = [&](int st, int k0) {
        uint32_t base = sb + (uint32_t)st * STAGE;
        const __half* asrc[2] = {Ahi, Alo};
        #pragma unroll
        for (int v = 0; v < AV; v++) {
            #pragma unroll
            for (int j = 0; j < 4; j++) {
                int idx = j * 256 + t;
                int row = idx >> 3, u = idx & 7;           // u = 16B unit (8 fp16)
                const __half* g = asrc[v] + (aRow0 + row) * (size_t)K + k0 + u * 8;
                cpasync16(base + v * A_SZ + (uint32_t)row * 128 + (uint32_t)((u ^ (row & 7)) << 4), g);
            }
        }
        const __half* bsrc[2] = {Bhi, Blo};
        #pragma unroll
        for (int v = 0; v < BV; v++) {
            #pragma unroll
            for (int j = 0; j < 8; j++) {
                int idx = j * 256 + t;
                int row = idx >> 3, u = idx & 7;
                const __half* g = bsrc[v] + (bRow0 + row) * (size_t)K + k0 + u * 8;
                cpasync16(base + AV * A_SZ + v * B_SZ + (uint32_t)row * 128 + (uint32_t)((u ^ (row & 7)) << 4), g);
            }
        }
    };

    #pragma unroll
    for (int s = 0; s < STAGES; s++) {
        load_stage(s, s * 64);
        cp_commit();
    }

    int stageIdx = 0;
    for (int c = 0; c < NS; c++) {
        asm volatile("cp.async.wait_group %0;" :: "n"(STAGES - 1) : "memory");
        __syncthreads();
        const uint32_t stb = (uint32_t)(stageIdx * STAGE);

        #pragma unroll
        for (int s = 0; s < 4; s++) {                      // k16 steps within k64
            const uint32_t aswz = (uint32_t)(((2 * s + aColBit) ^ r7) << 4);
            const uint32_t bswz = (uint32_t)(((2 * s + bColBit) ^ r7) << 4);

            uint32_t ah[4][4], al[4][4];
            #pragma unroll
            for (int mf = 0; mf < 4; mf++) {
                ldsm4(ah[mf], aBase[mf] + stb + aswz);
                if (AV == 2) ldsm4(al[mf], aBase[mf] + stb + A_SZ + aswz);
            }
            #pragma unroll
            for (int p = 0; p < 4; p++) {
                uint32_t bh[4];
                ldsm4(bh, bBase[p] + stb + bswz);
                if (AV == 2 && BV == 2) {
                    uint32_t bl[4];
                    ldsm4(bl, bBase[p] + stb + B_SZ + bswz);
                    #pragma unroll
                    for (int mf = 0; mf < 4; mf++) {
                        mma16(acc[mf][2 * p],     ah[mf], bh[0], bh[1]);
                        mma16(acc[mf][2 * p],     ah[mf], bl[0], bl[1]);
                        mma16(acc[mf][2 * p],     al[mf], bh[0], bh[1]);
                        mma16(acc[mf][2 * p + 1], ah[mf], bh[2], bh[3]);
                        mma16(acc[mf][2 * p + 1], ah[mf], bl[2], bl[3]);
                        mma16(acc[mf][2 * p + 1], al[mf], bh[2], bh[3]);
                    }
                } else if (AV == 2) {
                    #pragma unroll
                    for (int mf = 0; mf < 4; mf++) {
                        mma16(acc[mf][2 * p],     ah[mf], bh[0], bh[1]);
                        mma16(acc[mf][2 * p],     al[mf], bh[0], bh[1]);
                        mma16(acc[mf][2 * p + 1], ah[mf], bh[2], bh[3]);
                        mma16(acc[mf][2 * p + 1], al[mf], bh[2], bh[3]);
                    }
                } else {
                    #pragma unroll
                    for (int mf = 0; mf < 4; mf++) {
                        mma16(acc[mf][2 * p],     ah[mf], bh[0], bh[1]);
                        mma16(acc[mf][2 * p + 1], ah[mf], bh[2], bh[3]);
                    }
                }
            }
        }
        __syncthreads();
        if (c + STAGES < NS) load_stage(stageIdx, (c + STAGES) * 64);
        cp_commit();
        stageIdx = (stageIdx + 1 == STAGES) ? 0 : stageIdx + 1;
    }

    // epilogue
    float* obase = Out + ((size_t)b * aRows + blockIdx.y * 128 + wm * 64) * 2048
                       + blockIdx.x * 256 + wn * 64;
    const int rr = l >> 2, cc = (l & 3) * 2;
    #pragma unroll
    for (int mf = 0; mf < 4; mf++) {
        #pragma unroll
        for (int nf = 0; nf < 8; nf++) {
            int r = mf * 16 + rr;
            int c = nf * 8 + cc;
            *(float2*)(obase + (size_t)r * 2048 + c)       = make_float2(acc[mf][nf][0], acc[mf][nf][1]);
            *(float2*)(obase + (size_t)(r + 8) * 2048 + c) = make_float2(acc[mf][nf][2], acc[mf][nf][3]);
        }
    }
}

// ---------------------------------------------------------------------------
// Softmax over n2 per (b,n1) column, in place on S; also writes fp16
// transposed copy Bt[b][n1][n2] (coalesced via 32x32 smem tiles).
// block (32,8), grid (N1/32, B)
// ---------------------------------------------------------------------------
__global__ void softmax_kernel(float* __restrict__ S, __half* __restrict__ Bt)
{
    __shared__ float red_m[8][32], red_s[8][32];
    __shared__ float fin_m[32], fin_s[32];
    __shared__ float tile[32][33];

    const int x = threadIdx.x, y = threadIdx.y;
    const int b = blockIdx.y;
    const int n1b = blockIdx.x * 32;
    float* Sb = S + (size_t)b * N2_ * N1_ + n1b + x;

    float m = -FLT_MAX, s = 0.f;
    for (int n2 = y; n2 < N2_; n2 += 8) {
        float v = Sb[(size_t)n2 * N1_];
        float mn = fmaxf(m, v);
        s = s * __expf(m - mn) + __expf(v - mn);
        m = mn;
    }
    red_m[y][x] = m; red_s[y][x] = s;
    __syncthreads();
    if (y == 0) {
        float M = red_m[0][x], SS = red_s[0][x];
        #pragma unroll
        for (int j = 1; j < 8; j++) {
            float mj = red_m[j][x], sj = red_s[j][x];
            float mn = fmaxf(M, mj);
            SS = SS * __expf(M - mn) + sj * __expf(mj - mn);
            M = mn;
        }
        fin_m[x] = M; fin_s[x] = 1.0f / SS;
    }
    __syncthreads();
    const float M = fin_m[x], inv = fin_s[x];

    for (int t2 = 0; t2 < N2_; t2 += 32) {
        #pragma unroll
        for (int k = 0; k < 4; k++) {
            int r = t2 + y + 8 * k;
            float v = Sb[(size_t)r * N1_];
            float w = __expf(v - M) * inv;
            Sb[(size_t)r * N1_] = w;
            tile[y + 8 * k][x] = w;
        }
        __syncthreads();
        #pragma unroll
        for (int k = 0; k < 4; k++) {
            int ry = y + 8 * k;                       // local n1
            float w = tile[x][ry];
            Bt[((size_t)b * N1_ + n1b + ry) * N2_ + t2 + x] = __float2half_rn(w);
        }
        __syncthreads();
    }
}

// ---------------------------------------------------------------------------
// launch
// ---------------------------------------------------------------------------
extern "C" void kernel_launch(void* const* d_in, const int* in_sizes, int n_in,
                              void* d_out, int out_size)
{
    (void)in_sizes; (void)n_in; (void)out_size;
    const float* RI1 = (const float*)d_in[0];   // [B][C][N1]
    const float* RI2 = (const float*)d_in[1];   // [B][C][N2]
    const float* RE2 = (const float*)d_in[2];   // [B][D][N2]

    float* out   = (float*)d_out;
    float* embed = out;                                  // [B][D][N1]
    float* attn  = out + (size_t)B_ * D_ * N1_;          // [B][N2][N1]

    void *ri1h, *ri1l, *ri2h, *ri2l, *re2, *bt;
    cudaGetSymbolAddress(&ri1h, g_ri1t_hi);
    cudaGetSymbolAddress(&ri1l, g_ri1t_lo);
    cudaGetSymbolAddress(&ri2h, g_ri2t_hi);
    cudaGetSymbolAddress(&ri2l, g_ri2t_lo);
    cudaGetSymbolAddress(&re2,  g_re2);
    cudaGetSymbolAddress(&bt,   g_bt);

    constexpr int SMEM1 = 2 * (2 * 128 * 128 + 2 * 256 * 128);   // 196608
    constexpr int SMEM2 = 4 * (1 * 128 * 128 + 1 * 256 * 128);   // 196608
    cudaFuncSetAttribute((const void*)gemm_mma<512, 2, 2, 2>,
                         cudaFuncAttributeMaxDynamicSharedMemorySize, SMEM1);
    cudaFuncSetAttribute((const void*)gemm_mma<2048, 1, 1, 4>,
                         cudaFuncAttributeMaxDynamicSharedMemorySize, SMEM2);

    dim3 tb(32, 8);
    tsplit_kernel<<<dim3(N1_ / 32, C_ / 32, B_), tb>>>(
        RI1, (__half*)ri1h, (__half*)ri1l);
    tsplit_kernel<<<dim3(N2_ / 32, C_ / 32, B_), tb>>>(
        RI2, (__half*)ri2h, (__half*)ri2l);
    hconv_kernel<<<(B_ * D_ * N2_ / 4) / 256, 256>>>(
        (const float4*)RE2, (__half*)re2);

    // GEMM1: scores[b][n2][n1] = RI2T x RI1T (fp16 split, 3 products), K=512
    gemm_mma<512, 2, 2, 2><<<dim3(N1_ / 256, N2_ / 128, B_), 256, SMEM1>>>(
        (const __half*)ri2h, (const __half*)ri2l,
        (const __half*)ri1h, (const __half*)ri1l, attn, N2_);

    softmax_kernel<<<dim3(N1_ / 32, B_), tb>>>(attn, (__half*)bt);

    // GEMM2: embed[b][d][n1] = RE2(fp16) x attnT(fp16), 1 product, K=2048
    gemm_mma<2048, 1, 1, 4><<<dim3(N1_ / 256, D_ / 128, B_), 256, SMEM2>>>(
        (const __half*)re2, nullptr,
        (const __half*)bt, nullptr, embed, D_);
}

// round 8
// speedup vs baseline: 3.6115x; 1.0058x over previous
#include <cuda_runtime.h>
#include <cuda_fp16.h>
#include <cstdint>
#include <cfloat>

#define B_   16
#define C_   512
#define D_   512
#define N1_  2048
#define N2_  2048

// ---------------------------------------------------------------------------
// scratch (__device__ globals: allocation-free), fp16 operands
// ---------------------------------------------------------------------------
__device__ __align__(16) __half g_ri1t_hi[16 * 2048 * 512];
__device__ __align__(16) __half g_ri1t_lo[16 * 2048 * 512];
__device__ __align__(16) __half g_ri2t_hi[16 * 2048 * 512];
__device__ __align__(16) __half g_ri2t_lo[16 * 2048 * 512];
__device__ __align__(16) __half g_re2    [16 * 512 * 2048];
__device__ __align__(16) __half g_bt     [16 * 2048 * 2048];   // attn^T fp16

// ---------------------------------------------------------------------------
// helpers
// ---------------------------------------------------------------------------
__device__ __forceinline__ uint32_t smem_u32(const void* p) {
    uint32_t a;
    asm("{ .reg .u64 t; cvta.to.shared.u64 t, %1; cvt.u32.u64 %0, t; }" : "=r"(a) : "l"(p));
    return a;
}
__device__ __forceinline__ void cpasync16(uint32_t dst, const void* src) {
    asm volatile("cp.async.cg.shared.global [%0], [%1], 16;" :: "r"(dst), "l"(src));
}
__device__ __forceinline__ void cp_commit() {
    asm volatile("cp.async.commit_group;" ::: "memory");
}
__device__ __forceinline__ void ldsm4(uint32_t* r, uint32_t addr) {
    asm volatile("ldmatrix.sync.aligned.m8n8.x4.shared.b16 {%0,%1,%2,%3}, [%4];"
                 : "=r"(r[0]), "=r"(r[1]), "=r"(r[2]), "=r"(r[3]) : "r"(addr));
}
__device__ __forceinline__ void mma16(float* d, const uint32_t* a, uint32_t b0, uint32_t b1) {
    asm volatile("mma.sync.aligned.m16n8k16.row.col.f32.f16.f16.f32 "
                 "{%0,%1,%2,%3}, {%4,%5,%6,%7}, {%8,%9}, {%0,%1,%2,%3};"
                 : "+f"(d[0]), "+f"(d[1]), "+f"(d[2]), "+f"(d[3])
                 : "r"(a[0]), "r"(a[1]), "r"(a[2]), "r"(a[3]), "r"(b0), "r"(b1));
}
__device__ __forceinline__ void hsplit(float x, __half& h, __half& l) {
    h = __float2half_rn(x);
    l = __float2half_rn(x - __half2float(h));
}

// ---------------------------------------------------------------------------
// transpose + fp16 split: X[b][C][N] -> Thi/Tlo[b][N][C]
// ---------------------------------------------------------------------------
__global__ void tsplit_kernel(const float* __restrict__ X,
                              __half* __restrict__ Thi, __half* __restrict__ Tlo)
{
    __shared__ float tile[32][33];
    const int b = blockIdx.z;
    const int n0 = blockIdx.x * 32, c0 = blockIdx.y * 32;
    const int tx = threadIdx.x, ty = threadIdx.y;

    const size_t ib = (size_t)b * C_ * N1_;
    #pragma unroll
    for (int i = ty; i < 32; i += 8)
        tile[i][tx] = X[ib + (size_t)(c0 + i) * N1_ + n0 + tx];
    __syncthreads();

    const size_t ob = (size_t)b * N1_ * C_;
    #pragma unroll
    for (int i = ty; i < 32; i += 8) {
        float v = tile[tx][i];
        __half h, l; hsplit(v, h, l);
        size_t o = ob + (size_t)(n0 + i) * C_ + c0 + tx;
        Thi[o] = h; Tlo[o] = l;
    }
}

// plain fp16 convert (RE2): K-major already
__global__ void hconv_kernel(const float4* __restrict__ src,
                             __half* __restrict__ dst)
{
    const int i = blockIdx.x * blockDim.x + threadIdx.x;
    float4 v = src[i];
    __half2* D = (__half2*)(dst + (size_t)i * 4);
    D[0] = __half2(__float2half_rn(v.x), __float2half_rn(v.y));
    D[1] = __half2(__float2half_rn(v.z), __float2half_rn(v.w));
}

// ---------------------------------------------------------------------------
// fp16 GEMM via mma.sync m16n8k16.
// Out[b*aRows + m][n] (n-stride 2048) = sum_k A[row][k] * B[row][k]
// AV/BV = number of split versions per operand.
//   AV2,BV2 -> 3 products (hh+hl+lh);  AV1,BV1 -> 1 product.
// Block 128(M) x 256(N), 16 warps (512 thr), warptile 32x64 (wm 0..3, wn 0..3),
// k-chunk 64, STAGES smem buffers.
// ---------------------------------------------------------------------------
template<int K, int AV, int BV, int STAGES>
__global__ __launch_bounds__(512)
void gemm_mma(const __half* __restrict__ Ahi, const __half* __restrict__ Alo,
              const __half* __restrict__ Bhi, const __half* __restrict__ Blo,
              float* __restrict__ Out, int aRows)
{
    extern __shared__ __align__(128) char smem[];
    constexpr int A_SZ  = 128 * 128;              // bytes per A version
    constexpr int B_SZ  = 256 * 128;              // bytes per B version
    constexpr int STAGE = AV * A_SZ + BV * B_SZ;
    constexpr int NS    = K / 64;                 // k-chunk = 64 fp16 = 128B row

    const int t   = threadIdx.x;
    const int l   = t & 31;
    const int wid = t >> 5;
    const int wm  = wid >> 2;      // 0..3  (M: wm*32)
    const int wn  = wid & 3;       // 0..3  (N: wn*64)
    const uint32_t sb = smem_u32(smem);

    const int b = blockIdx.z;
    const size_t aRow0 = (size_t)b * aRows + blockIdx.y * 128;
    const size_t bRow0 = (size_t)b * 2048  + blockIdx.x * 256;

    uint32_t aBase[2], bBase[4];
    {
        int ra = wm * 32 + (l & 7) + ((l >> 3) & 1) * 8;
        #pragma unroll
        for (int mf = 0; mf < 2; mf++) aBase[mf] = sb + (uint32_t)(ra + mf * 16) * 128;
        int rb = wn * 64 + (l & 7) + ((l >> 4) & 1) * 8;
        #pragma unroll
        for (int p = 0; p < 4; p++)  bBase[p]  = sb + AV * A_SZ + (uint32_t)(rb + p * 16) * 128;
    }
    const int aColBit = (l >> 4) & 1;
    const int bColBit = (l >> 3) & 1;
    const int r7 = l & 7;

    float acc[2][8][4];
    #pragma unroll
    for (int i = 0; i < 2; i++)
        #pragma unroll
        for (int j = 0; j < 8; j++)
            #pragma unroll
            for (int q = 0; q < 4; q++) acc[i][j][q] = 0.f;

    auto load_stage = [&](int st, int k0) {
        uint32_t base = sb + (uint32_t)st * STAGE;
        const __half* asrc[2] = {Ahi, Alo};
        #pragma unroll
        for (int v = 0; v < AV; v++) {
            #pragma unroll
            for (int j = 0; j < 2; j++) {
                int idx = j * 512 + t;
                int row = idx >> 3, u = idx & 7;           // u = 16B unit (8 fp16)
                const __half* g = asrc[v] + (aRow0 + row) * (size_t)K + k0 + u * 8;
                cpasync16(base + v * A_SZ + (uint32_t)row * 128 + (uint32_t)((u ^ (row & 7)) << 4), g);
            }
        }
        const __half* bsrc[2] = {Bhi, Blo};
        #pragma unroll
        for (int v = 0; v < BV; v++) {
            #pragma unroll
            for (int j = 0; j < 4; j++) {
                int idx = j * 512 + t;
                int row = idx >> 3, u = idx & 7;
                const __half* g = bsrc[v] + (bRow0 + row) * (size_t)K + k0 + u * 8;
                cpasync16(base + AV * A_SZ + v * B_SZ + (uint32_t)row * 128 + (uint32_t)((u ^ (row & 7)) << 4), g);
            }
        }
    };

    #pragma unroll
    for (int s = 0; s < STAGES; s++) {
        load_stage(s, s * 64);
        cp_commit();
    }

    int stageIdx = 0;
    for (int c = 0; c < NS; c++) {
        asm volatile("cp.async.wait_group %0;" :: "n"(STAGES - 1) : "memory");
        __syncthreads();
        const uint32_t stb = (uint32_t)(stageIdx * STAGE);

        #pragma unroll
        for (int s = 0; s < 4; s++) {                      // k16 steps within k64
            const uint32_t aswz = (uint32_t)(((2 * s + aColBit) ^ r7) << 4);
            const uint32_t bswz = (uint32_t)(((2 * s + bColBit) ^ r7) << 4);

            uint32_t ah[2][4], al[2][4];
            #pragma unroll
            for (int mf = 0; mf < 2; mf++) {
                ldsm4(ah[mf], aBase[mf] + stb + aswz);
                if (AV == 2) ldsm4(al[mf], aBase[mf] + stb + A_SZ + aswz);
            }
            #pragma unroll
            for (int p = 0; p < 4; p++) {
                uint32_t bh[4];
                ldsm4(bh, bBase[p] + stb + bswz);
                if (AV == 2 && BV == 2) {
                    uint32_t bl[4];
                    ldsm4(bl, bBase[p] + stb + B_SZ + bswz);
                    #pragma unroll
                    for (int mf = 0; mf < 2; mf++) {
                        mma16(acc[mf][2 * p],     ah[mf], bh[0], bh[1]);
                        mma16(acc[mf][2 * p],     ah[mf], bl[0], bl[1]);
                        mma16(acc[mf][2 * p],     al[mf], bh[0], bh[1]);
                        mma16(acc[mf][2 * p + 1], ah[mf], bh[2], bh[3]);
                        mma16(acc[mf][2 * p + 1], ah[mf], bl[2], bl[3]);
                        mma16(acc[mf][2 * p + 1], al[mf], bh[2], bh[3]);
                    }
                } else if (AV == 2) {
                    #pragma unroll
                    for (int mf = 0; mf < 2; mf++) {
                        mma16(acc[mf][2 * p],     ah[mf], bh[0], bh[1]);
                        mma16(acc[mf][2 * p],     al[mf], bh[0], bh[1]);
                        mma16(acc[mf][2 * p + 1], ah[mf], bh[2], bh[3]);
                        mma16(acc[mf][2 * p + 1], al[mf], bh[2], bh[3]);
                    }
                } else {
                    #pragma unroll
                    for (int mf = 0; mf < 2; mf++) {
                        mma16(acc[mf][2 * p],     ah[mf], bh[0], bh[1]);
                        mma16(acc[mf][2 * p + 1], ah[mf], bh[2], bh[3]);
                    }
                }
            }
        }
        __syncthreads();
        if (c + STAGES < NS) load_stage(stageIdx, (c + STAGES) * 64);
        cp_commit();
        stageIdx = (stageIdx + 1 == STAGES) ? 0 : stageIdx + 1;
    }

    // epilogue
    float* obase = Out + ((size_t)b * aRows + blockIdx.y * 128 + wm * 32) * 2048
                       + blockIdx.x * 256 + wn * 64;
    const int rr = l >> 2, cc = (l & 3) * 2;
    #pragma unroll
    for (int mf = 0; mf < 2; mf++) {
        #pragma unroll
        for (int nf = 0; nf < 8; nf++) {
            int r = mf * 16 + rr;
            int c = nf * 8 + cc;
            *(float2*)(obase + (size_t)r * 2048 + c)       = make_float2(acc[mf][nf][0], acc[mf][nf][1]);
            *(float2*)(obase + (size_t)(r + 8) * 2048 + c) = make_float2(acc[mf][nf][2], acc[mf][nf][3]);
        }
    }
}

// ---------------------------------------------------------------------------
// Softmax over n2 per (b,n1) column, in place on S; also writes fp16
// transposed copy Bt[b][n1][n2] (coalesced via 32x32 smem tiles).
// block (32,8), grid (N1/32, B)
// ---------------------------------------------------------------------------
__global__ void softmax_kernel(float* __restrict__ S, __half* __restrict__ Bt)
{
    __shared__ float red_m[8][32], red_s[8][32];
    __shared__ float fin_m[32], fin_s[32];
    __shared__ float tile[32][33];

    const int x = threadIdx.x, y = threadIdx.y;
    const int b = blockIdx.y;
    const int n1b = blockIdx.x * 32;
    float* Sb = S + (size_t)b * N2_ * N1_ + n1b + x;

    float m = -FLT_MAX, s = 0.f;
    for (int n2 = y; n2 < N2_; n2 += 8) {
        float v = Sb[(size_t)n2 * N1_];
        float mn = fmaxf(m, v);
        s = s * __expf(m - mn) + __expf(v - mn);
        m = mn;
    }
    red_m[y][x] = m; red_s[y][x] = s;
    __syncthreads();
    if (y == 0) {
        float M = red_m[0][x], SS = red_s[0][x];
        #pragma unroll
        for (int j = 1; j < 8; j++) {
            float mj = red_m[j][x], sj = red_s[j][x];
            float mn = fmaxf(M, mj);
            SS = SS * __expf(M - mn) + sj * __expf(mj - mn);
            M = mn;
        }
        fin_m[x] = M; fin_s[x] = 1.0f / SS;
    }
    __syncthreads();
    const float M = fin_m[x], inv = fin_s[x];

    for (int t2 = 0; t2 < N2_; t2 += 32) {
        #pragma unroll
        for (int k = 0; k < 4; k++) {
            int r = t2 + y + 8 * k;
            float v = Sb[(size_t)r * N1_];
            float w = __expf(v - M) * inv;
            Sb[(size_t)r * N1_] = w;
            tile[y + 8 * k][x] = w;
        }
        __syncthreads();
        #pragma unroll
        for (int k = 0; k < 4; k++) {
            int ry = y + 8 * k;                       // local n1
            float w = tile[x][ry];
            Bt[((size_t)b * N1_ + n1b + ry) * N2_ + t2 + x] = __float2half_rn(w);
        }
        __syncthreads();
    }
}

// ---------------------------------------------------------------------------
// launch
// ---------------------------------------------------------------------------
extern "C" void kernel_launch(void* const* d_in, const int* in_sizes, int n_in,
                              void* d_out, int out_size)
{
    (void)in_sizes; (void)n_in; (void)out_size;
    const float* RI1 = (const float*)d_in[0];   // [B][C][N1]
    const float* RI2 = (const float*)d_in[1];   // [B][C][N2]
    const float* RE2 = (const float*)d_in[2];   // [B][D][N2]

    float* out   = (float*)d_out;
    float* embed = out;                                  // [B][D][N1]
    float* attn  = out + (size_t)B_ * D_ * N1_;          // [B][N2][N1]

    void *ri1h, *ri1l, *ri2h, *ri2l, *re2, *bt;
    cudaGetSymbolAddress(&ri1h, g_ri1t_hi);
    cudaGetSymbolAddress(&ri1l, g_ri1t_lo);
    cudaGetSymbolAddress(&ri2h, g_ri2t_hi);
    cudaGetSymbolAddress(&ri2l, g_ri2t_lo);
    cudaGetSymbolAddress(&re2,  g_re2);
    cudaGetSymbolAddress(&bt,   g_bt);

    constexpr int SMEM1 = 2 * (2 * 128 * 128 + 2 * 256 * 128);   // 196608
    constexpr int SMEM2 = 4 * (1 * 128 * 128 + 1 * 256 * 128);   // 196608
    cudaFuncSetAttribute((const void*)gemm_mma<512, 2, 2, 2>,
                         cudaFuncAttributeMaxDynamicSharedMemorySize, SMEM1);
    cudaFuncSetAttribute((const void*)gemm_mma<2048, 1, 1, 4>,
                         cudaFuncAttributeMaxDynamicSharedMemorySize, SMEM2);

    dim3 tb(32, 8);
    tsplit_kernel<<<dim3(N1_ / 32, C_ / 32, B_), tb>>>(
        RI1, (__half*)ri1h, (__half*)ri1l);
    tsplit_kernel<<<dim3(N2_ / 32, C_ / 32, B_), tb>>>(
        RI2, (__half*)ri2h, (__half*)ri2l);
    hconv_kernel<<<(B_ * D_ * N2_ / 4) / 256, 256>>>(
        (const float4*)RE2, (__half*)re2);

    // GEMM1: scores[b][n2][n1] = RI2T x RI1T (fp16 split, 3 products), K=512
    gemm_mma<512, 2, 2, 2><<<dim3(N1_ / 256, N2_ / 128, B_), 512, SMEM1>>>(
        (const __half*)ri2h, (const __half*)ri2l,
        (const __half*)ri1h, (const __half*)ri1l, attn, N2_);

    softmax_kernel<<<dim3(N1_ / 32, B_), tb>>>(attn, (__half*)bt);

    // GEMM2: embed[b][d][n1] = RE2(fp16) x attnT(fp16), 1 product, K=2048
    gemm_mma<2048, 1, 1, 4><<<dim3(N1_ / 256, D_ / 128, B_), 512, SMEM2>>>(
        (const __half*)re2, nullptr,
        (const __half*)bt, nullptr, embed, D_);
}

// round 9
// speedup vs baseline: 3.6223x; 1.0030x over previous
#include <cuda_runtime.h>
#include <cuda_fp16.h>
#include <cstdint>
#include <cfloat>

#define B_   16
#define C_   512
#define D_   512
#define N1_  2048
#define N2_  2048

// ---------------------------------------------------------------------------
// scratch (__device__ globals: allocation-free), fp16 operands
// ---------------------------------------------------------------------------
__device__ __align__(16) __half g_ri1t_hi[16 * 2048 * 512];
__device__ __align__(16) __half g_ri1t_lo[16 * 2048 * 512];
__device__ __align__(16) __half g_ri2t_hi[16 * 2048 * 512];
__device__ __align__(16) __half g_ri2t_lo[16 * 2048 * 512];
__device__ __align__(16) __half g_re2    [16 * 512 * 2048];
__device__ __align__(16) __half g_bt     [16 * 2048 * 2048];   // attn^T fp16

// ---------------------------------------------------------------------------
// helpers
// ---------------------------------------------------------------------------
__device__ __forceinline__ uint32_t smem_u32(const void* p) {
    uint32_t a;
    asm("{ .reg .u64 t; cvta.to.shared.u64 t, %1; cvt.u32.u64 %0, t; }" : "=r"(a) : "l"(p));
    return a;
}
__device__ __forceinline__ void cpasync16(uint32_t dst, const void* src) {
    asm volatile("cp.async.cg.shared.global [%0], [%1], 16;" :: "r"(dst), "l"(src));
}
__device__ __forceinline__ void cp_commit() {
    asm volatile("cp.async.commit_group;" ::: "memory");
}
__device__ __forceinline__ void ldsm4(uint32_t* r, uint32_t addr) {
    asm volatile("ldmatrix.sync.aligned.m8n8.x4.shared.b16 {%0,%1,%2,%3}, [%4];"
                 : "=r"(r[0]), "=r"(r[1]), "=r"(r[2]), "=r"(r[3]) : "r"(addr));
}
__device__ __forceinline__ void mma16(float* d, const uint32_t* a, uint32_t b0, uint32_t b1) {
    asm volatile("mma.sync.aligned.m16n8k16.row.col.f32.f16.f16.f32 "
                 "{%0,%1,%2,%3}, {%4,%5,%6,%7}, {%8,%9}, {%0,%1,%2,%3};"
                 : "+f"(d[0]), "+f"(d[1]), "+f"(d[2]), "+f"(d[3])
                 : "r"(a[0]), "r"(a[1]), "r"(a[2]), "r"(a[3]), "r"(b0), "r"(b1));
}
__device__ __forceinline__ void hsplit(float x, __half& h, __half& l) {
    h = __float2half_rn(x);
    l = __float2half_rn(x - __half2float(h));
}

// ---------------------------------------------------------------------------
// transpose + fp16 split: X[b][C][N] -> Thi/Tlo[b][N][C]
// ---------------------------------------------------------------------------
__global__ void tsplit_kernel(const float* __restrict__ X,
                              __half* __restrict__ Thi, __half* __restrict__ Tlo)
{
    __shared__ float tile[32][33];
    const int b = blockIdx.z;
    const int n0 = blockIdx.x * 32, c0 = blockIdx.y * 32;
    const int tx = threadIdx.x, ty = threadIdx.y;

    const size_t ib = (size_t)b * C_ * N1_;
    #pragma unroll
    for (int i = ty; i < 32; i += 8)
        tile[i][tx] = X[ib + (size_t)(c0 + i) * N1_ + n0 + tx];
    __syncthreads();

    const size_t ob = (size_t)b * N1_ * C_;
    #pragma unroll
    for (int i = ty; i < 32; i += 8) {
        float v = tile[tx][i];
        __half h, l; hsplit(v, h, l);
        size_t o = ob + (size_t)(n0 + i) * C_ + c0 + tx;
        Thi[o] = h; Tlo[o] = l;
    }
}

// plain fp16 convert (RE2): K-major already
__global__ void hconv_kernel(const float4* __restrict__ src,
                             __half* __restrict__ dst)
{
    const int i = blockIdx.x * blockDim.x + threadIdx.x;
    float4 v = src[i];
    __half2* D = (__half2*)(dst + (size_t)i * 4);
    D[0] = __half2(__float2half_rn(v.x), __float2half_rn(v.y));
    D[1] = __half2(__float2half_rn(v.z), __float2half_rn(v.w));
}

// ---------------------------------------------------------------------------
// fp16 GEMM via mma.sync m16n8k16. Single-sync multistage pipeline.
// Out[b*aRows + m][n] (n-stride 2048) = sum_k A[row][k] * B[row][k]
// AV/BV = split versions per operand (AV2,BV2: 3 products; AV1,BV1: 1).
// Block 128(M) x 256(N), 16 warps, warptile 32x64, k-chunk 64.
// ---------------------------------------------------------------------------
template<int K, int AV, int BV, int STAGES>
__global__ __launch_bounds__(512)
void gemm_mma(const __half* __restrict__ Ahi, const __half* __restrict__ Alo,
              const __half* __restrict__ Bhi, const __half* __restrict__ Blo,
              float* __restrict__ Out, int aRows)
{
    extern __shared__ __align__(128) char smem[];
    constexpr int A_SZ  = 128 * 128;              // bytes per A version
    constexpr int B_SZ  = 256 * 128;              // bytes per B version
    constexpr int STAGE = AV * A_SZ + BV * B_SZ;
    constexpr int NS    = K / 64;                 // k-chunk = 64 fp16 = 128B row

    const int t   = threadIdx.x;
    const int l   = t & 31;
    const int wid = t >> 5;
    const int wm  = wid >> 2;      // 0..3  (M: wm*32)
    const int wn  = wid & 3;       // 0..3  (N: wn*64)
    const uint32_t sb = smem_u32(smem);

    const int b = blockIdx.z;
    const size_t aRow0 = (size_t)b * aRows + blockIdx.y * 128;
    const size_t bRow0 = (size_t)b * 2048  + blockIdx.x * 256;

    uint32_t aBase[2], bBase[4];
    {
        int ra = wm * 32 + (l & 7) + ((l >> 3) & 1) * 8;
        #pragma unroll
        for (int mf = 0; mf < 2; mf++) aBase[mf] = sb + (uint32_t)(ra + mf * 16) * 128;
        int rb = wn * 64 + (l & 7) + ((l >> 4) & 1) * 8;
        #pragma unroll
        for (int p = 0; p < 4; p++)  bBase[p]  = sb + AV * A_SZ + (uint32_t)(rb + p * 16) * 128;
    }
    const int aColBit = (l >> 4) & 1;
    const int bColBit = (l >> 3) & 1;
    const int r7 = l & 7;

    float acc[2][8][4];
    #pragma unroll
    for (int i = 0; i < 2; i++)
        #pragma unroll
        for (int j = 0; j < 8; j++)
            #pragma unroll
            for (int q = 0; q < 4; q++) acc[i][j][q] = 0.f;

    auto load_stage = [&](int st, int k0) {
        uint32_t base = sb + (uint32_t)st * STAGE;
        const __half* asrc[2] = {Ahi, Alo};
        #pragma unroll
        for (int v = 0; v < AV; v++) {
            #pragma unroll
            for (int j = 0; j < 2; j++) {
                int idx = j * 512 + t;
                int row = idx >> 3, u = idx & 7;           // u = 16B unit (8 fp16)
                const __half* g = asrc[v] + (aRow0 + row) * (size_t)K + k0 + u * 8;
                cpasync16(base + v * A_SZ + (uint32_t)row * 128 + (uint32_t)((u ^ (row & 7)) << 4), g);
            }
        }
        const __half* bsrc[2] = {Bhi, Blo};
        #pragma unroll
        for (int v = 0; v < BV; v++) {
            #pragma unroll
            for (int j = 0; j < 4; j++) {
                int idx = j * 512 + t;
                int row = idx >> 3, u = idx & 7;
                const __half* g = bsrc[v] + (bRow0 + row) * (size_t)K + k0 + u * 8;
                cpasync16(base + AV * A_SZ + v * B_SZ + (uint32_t)row * 128 + (uint32_t)((u ^ (row & 7)) << 4), g);
            }
        }
    };

    // prefetch STAGES-1 stages (one slot stays free for in-loop prefetch)
    #pragma unroll
    for (int s = 0; s < STAGES - 1; s++) {
        load_stage(s, s * 64);
        cp_commit();
    }

    for (int c = 0; c < NS; c++) {
        // stage c ready when <= STAGES-2 groups outstanding
        asm volatile("cp.async.wait_group %0;" :: "n"(STAGES - 2) : "memory");
        __syncthreads();   // all warps done reading slot (c-1)%S -> safe to refill

        const int ps = c + STAGES - 1;
        if (ps < NS) load_stage(ps % STAGES, ps * 64);
        cp_commit();

        const uint32_t stb = (uint32_t)((c % STAGES) * STAGE);

        #pragma unroll
        for (int s = 0; s < 4; s++) {                      // k16 steps within k64
            const uint32_t aswz = (uint32_t)(((2 * s + aColBit) ^ r7) << 4);
            const uint32_t bswz = (uint32_t)(((2 * s + bColBit) ^ r7) << 4);

            uint32_t ah[2][4], al[2][4];
            #pragma unroll
            for (int mf = 0; mf < 2; mf++) {
                ldsm4(ah[mf], aBase[mf] + stb + aswz);
                if (AV == 2) ldsm4(al[mf], aBase[mf] + stb + A_SZ + aswz);
            }
            #pragma unroll
            for (int p = 0; p < 4; p++) {
                uint32_t bh[4];
                ldsm4(bh, bBase[p] + stb + bswz);
                if (AV == 2 && BV == 2) {
                    uint32_t bl[4];
                    ldsm4(bl, bBase[p] + stb + B_SZ + bswz);
                    #pragma unroll
                    for (int mf = 0; mf < 2; mf++) {
                        mma16(acc[mf][2 * p],     ah[mf], bh[0], bh[1]);
                        mma16(acc[mf][2 * p],     ah[mf], bl[0], bl[1]);
                        mma16(acc[mf][2 * p],     al[mf], bh[0], bh[1]);
                        mma16(acc[mf][2 * p + 1], ah[mf], bh[2], bh[3]);
                        mma16(acc[mf][2 * p + 1], ah[mf], bl[2], bl[3]);
                        mma16(acc[mf][2 * p + 1], al[mf], bh[2], bh[3]);
                    }
                } else if (AV == 2) {
                    #pragma unroll
                    for (int mf = 0; mf < 2; mf++) {
                        mma16(acc[mf][2 * p],     ah[mf], bh[0], bh[1]);
                        mma16(acc[mf][2 * p],     al[mf], bh[0], bh[1]);
                        mma16(acc[mf][2 * p + 1], ah[mf], bh[2], bh[3]);
                        mma16(acc[mf][2 * p + 1], al[mf], bh[2], bh[3]);
                    }
                } else {
                    #pragma unroll
                    for (int mf = 0; mf < 2; mf++) {
                        mma16(acc[mf][2 * p],     ah[mf], bh[0], bh[1]);
                        mma16(acc[mf][2 * p + 1], ah[mf], bh[2], bh[3]);
                    }
                }
            }
        }
    }

    // epilogue
    float* obase = Out + ((size_t)b * aRows + blockIdx.y * 128 + wm * 32) * 2048
                       + blockIdx.x * 256 + wn * 64;
    const int rr = l >> 2, cc = (l & 3) * 2;
    #pragma unroll
    for (int mf = 0; mf < 2; mf++) {
        #pragma unroll
        for (int nf = 0; nf < 8; nf++) {
            int r = mf * 16 + rr;
            int c = nf * 8 + cc;
            *(float2*)(obase + (size_t)r * 2048 + c)       = make_float2(acc[mf][nf][0], acc[mf][nf][1]);
            *(float2*)(obase + (size_t)(r + 8) * 2048 + c) = make_float2(acc[mf][nf][2], acc[mf][nf][3]);
        }
    }
}

// ---------------------------------------------------------------------------
// Softmax over n2 per (b,n1) column, in place on S; also writes fp16
// transposed copy Bt[b][n1][n2] (coalesced via 32x32 smem tiles).
// block (32,8), grid (N1/32, B).  Pass 1 uses ~1 expf/element (branchy max).
// ---------------------------------------------------------------------------
__global__ void softmax_kernel(float* __restrict__ S, __half* __restrict__ Bt)
{
    __shared__ float red_m[8][32], red_s[8][32];
    __shared__ float fin_m[32], fin_s[32];
    __shared__ float tile[32][33];

    const int x = threadIdx.x, y = threadIdx.y;
    const int b = blockIdx.y;
    const int n1b = blockIdx.x * 32;
    float* Sb = S + (size_t)b * N2_ * N1_ + n1b + x;

    float m = -FLT_MAX, s = 0.f;
    for (int n2 = y; n2 < N2_; n2 += 8) {
        float v = Sb[(size_t)n2 * N1_];
        if (v <= m) {
            s += __expf(v - m);
        } else {
            s = s * __expf(m - v) + 1.0f;
            m = v;
        }
    }
    red_m[y][x] = m; red_s[y][x] = s;
    __syncthreads();
    if (y == 0) {
        float M = red_m[0][x], SS = red_s[0][x];
        #pragma unroll
        for (int j = 1; j < 8; j++) {
            float mj = red_m[j][x], sj = red_s[j][x];
            float mn = fmaxf(M, mj);
            SS = SS * __expf(M - mn) + sj * __expf(mj - mn);
            M = mn;
        }
        fin_m[x] = M; fin_s[x] = 1.0f / SS;
    }
    __syncthreads();
    const float M = fin_m[x], inv = fin_s[x];

    for (int t2 = 0; t2 < N2_; t2 += 32) {
        #pragma unroll
        for (int k = 0; k < 4; k++) {
            int r = t2 + y + 8 * k;
            float v = Sb[(size_t)r * N1_];
            float w = __expf(v - M) * inv;
            Sb[(size_t)r * N1_] = w;
            tile[y + 8 * k][x] = w;
        }
        __syncthreads();
        #pragma unroll
        for (int k = 0; k < 4; k++) {
            int ry = y + 8 * k;                       // local n1
            float w = tile[x][ry];
            Bt[((size_t)b * N1_ + n1b + ry) * N2_ + t2 + x] = __float2half_rn(w);
        }
        __syncthreads();
    }
}

// ---------------------------------------------------------------------------
// launch
// ---------------------------------------------------------------------------
extern "C" void kernel_launch(void* const* d_in, const int* in_sizes, int n_in,
                              void* d_out, int out_size)
{
    (void)in_sizes; (void)n_in; (void)out_size;
    const float* RI1 = (const float*)d_in[0];   // [B][C][N1]
    const float* RI2 = (const float*)d_in[1];   // [B][C][N2]
    const float* RE2 = (const float*)d_in[2];   // [B][D][N2]

    float* out   = (float*)d_out;
    float* embed = out;                                  // [B][D][N1]
    float* attn  = out + (size_t)B_ * D_ * N1_;          // [B][N2][N1]

    void *ri1h, *ri1l, *ri2h, *ri2l, *re2, *bt;
    cudaGetSymbolAddress(&ri1h, g_ri1t_hi);
    cudaGetSymbolAddress(&ri1l, g_ri1t_lo);
    cudaGetSymbolAddress(&ri2h, g_ri2t_hi);
    cudaGetSymbolAddress(&ri2l, g_ri2t_lo);
    cudaGetSymbolAddress(&re2,  g_re2);
    cudaGetSymbolAddress(&bt,   g_bt);

    constexpr int SMEM1 = 2 * (2 * 128 * 128 + 2 * 256 * 128);   // 196608
    constexpr int SMEM2 = 4 * (1 * 128 * 128 + 1 * 256 * 128);   // 196608
    cudaFuncSetAttribute((const void*)gemm_mma<512, 2, 2, 2>,
                         cudaFuncAttributeMaxDynamicSharedMemorySize, SMEM1);
    cudaFuncSetAttribute((const void*)gemm_mma<2048, 1, 1, 4>,
                         cudaFuncAttributeMaxDynamicSharedMemorySize, SMEM2);

    dim3 tb(32, 8);
    tsplit_kernel<<<dim3(N1_ / 32, C_ / 32, B_), tb>>>(
        RI1, (__half*)ri1h, (__half*)ri1l);
    tsplit_kernel<<<dim3(N2_ / 32, C_ / 32, B_), tb>>>(
        RI2, (__half*)ri2h, (__half*)ri2l);
    hconv_kernel<<<(B_ * D_ * N2_ / 4) / 256, 256>>>(
        (const float4*)RE2, (__half*)re2);

    // GEMM1: scores[b][n2][n1] = RI2T x RI1T (fp16 split, 3 products), K=512
    gemm_mma<512, 2, 2, 2><<<dim3(N1_ / 256, N2_ / 128, B_), 512, SMEM1>>>(
        (const __half*)ri2h, (const __half*)ri2l,
        (const __half*)ri1h, (const __half*)ri1l, attn, N2_);

    softmax_kernel<<<dim3(N1_ / 32, B_), tb>>>(attn, (__half*)bt);

    // GEMM2: embed[b][d][n1] = RE2(fp16) x attnT(fp16), 1 product, K=2048
    gemm_mma<2048, 1, 1, 4><<<dim3(N1_ / 256, D_ / 128, B_), 512, SMEM2>>>(
        (const __half*)re2, nullptr,
        (const __half*)bt, nullptr, embed, D_);
}

// round 10
// speedup vs baseline: 3.6761x; 1.0149x over previous
#include <cuda_runtime.h>
#include <cuda_fp16.h>
#include <cstdint>
#include <cfloat>

#define B_   16
#define C_   512
#define D_   512
#define N1_  2048
#define N2_  2048

// ---------------------------------------------------------------------------
// scratch (__device__ globals: allocation-free), fp16 operands
// ---------------------------------------------------------------------------
__device__ __align__(16) __half g_ri1t_hi[16 * 2048 * 512];
__device__ __align__(16) __half g_ri1t_lo[16 * 2048 * 512];
__device__ __align__(16) __half g_ri2t_hi[16 * 2048 * 512];
__device__ __align__(16) __half g_ri2t_lo[16 * 2048 * 512];
__device__ __align__(16) __half g_re2    [16 * 512 * 2048];
__device__ __align__(16) __half g_bt     [16 * 2048 * 2048];   // attn^T fp16
__device__ __align__(16) float2 g_part   [16 * 16 * 2048];     // per-tile (max, sumexp)
__device__ __align__(16) float2 g_stats  [16 * 2048];          // final (max, 1/sum)

// ---------------------------------------------------------------------------
// helpers
// ---------------------------------------------------------------------------
__device__ __forceinline__ uint32_t smem_u32(const void* p) {
    uint32_t a;
    asm("{ .reg .u64 t; cvta.to.shared.u64 t, %1; cvt.u32.u64 %0, t; }" : "=r"(a) : "l"(p));
    return a;
}
__device__ __forceinline__ void cpasync16(uint32_t dst, const void* src) {
    asm volatile("cp.async.cg.shared.global [%0], [%1], 16;" :: "r"(dst), "l"(src));
}
__device__ __forceinline__ void cp_commit() {
    asm volatile("cp.async.commit_group;" ::: "memory");
}
__device__ __forceinline__ void ldsm4(uint32_t* r, uint32_t addr) {
    asm volatile("ldmatrix.sync.aligned.m8n8.x4.shared.b16 {%0,%1,%2,%3}, [%4];"
                 : "=r"(r[0]), "=r"(r[1]), "=r"(r[2]), "=r"(r[3]) : "r"(addr));
}
__device__ __forceinline__ void mma16(float* d, const uint32_t* a, uint32_t b0, uint32_t b1) {
    asm volatile("mma.sync.aligned.m16n8k16.row.col.f32.f16.f16.f32 "
                 "{%0,%1,%2,%3}, {%4,%5,%6,%7}, {%8,%9}, {%0,%1,%2,%3};"
                 : "+f"(d[0]), "+f"(d[1]), "+f"(d[2]), "+f"(d[3])
                 : "r"(a[0]), "r"(a[1]), "r"(a[2]), "r"(a[3]), "r"(b0), "r"(b1));
}
__device__ __forceinline__ void hsplit(float x, __half& h, __half& l) {
    h = __float2half_rn(x);
    l = __float2half_rn(x - __half2float(h));
}

// ---------------------------------------------------------------------------
// transpose + fp16 split: X[b][C][N] -> Thi/Tlo[b][N][C]
// ---------------------------------------------------------------------------
__global__ void tsplit_kernel(const float* __restrict__ X,
                              __half* __restrict__ Thi, __half* __restrict__ Tlo)
{
    __shared__ float tile[32][33];
    const int b = blockIdx.z;
    const int n0 = blockIdx.x * 32, c0 = blockIdx.y * 32;
    const int tx = threadIdx.x, ty = threadIdx.y;

    const size_t ib = (size_t)b * C_ * N1_;
    #pragma unroll
    for (int i = ty; i < 32; i += 8)
        tile[i][tx] = X[ib + (size_t)(c0 + i) * N1_ + n0 + tx];
    __syncthreads();

    const size_t ob = (size_t)b * N1_ * C_;
    #pragma unroll
    for (int i = ty; i < 32; i += 8) {
        float v = tile[tx][i];
        __half h, l; hsplit(v, h, l);
        size_t o = ob + (size_t)(n0 + i) * C_ + c0 + tx;
        Thi[o] = h; Tlo[o] = l;
    }
}

// plain fp16 convert (RE2): K-major already
__global__ void hconv_kernel(const float4* __restrict__ src,
                             __half* __restrict__ dst)
{
    const int i = blockIdx.x * blockDim.x + threadIdx.x;
    float4 v = src[i];
    __half2* D = (__half2*)(dst + (size_t)i * 4);
    D[0] = __half2(__float2half_rn(v.x), __float2half_rn(v.y));
    D[1] = __half2(__float2half_rn(v.z), __float2half_rn(v.w));
}

// ---------------------------------------------------------------------------
// fp16 GEMM via mma.sync m16n8k16. Single-sync multistage pipeline.
// Out[b*aRows + m][n] (n-stride 2048) = sum_k A[row][k] * B[row][k]
// AV/BV = split versions per operand (AV2,BV2: 3 products; AV1,BV1: 1).
// Block 128(M) x 256(N), 16 warps, warptile 32x64, k-chunk 64.
// STATS: epilogue also emits per-tile column (max, sumexp) into Part.
// ---------------------------------------------------------------------------
template<int K, int AV, int BV, int STAGES, bool STATS>
__global__ __launch_bounds__(512)
void gemm_mma(const __half* __restrict__ Ahi, const __half* __restrict__ Alo,
              const __half* __restrict__ Bhi, const __half* __restrict__ Blo,
              float* __restrict__ Out, float2* __restrict__ Part, int aRows)
{
    extern __shared__ __align__(128) char smem[];
    constexpr int A_SZ  = 128 * 128;              // bytes per A version
    constexpr int B_SZ  = 256 * 128;              // bytes per B version
    constexpr int STAGE = AV * A_SZ + BV * B_SZ;
    constexpr int NS    = K / 64;                 // k-chunk = 64 fp16 = 128B row

    const int t   = threadIdx.x;
    const int l   = t & 31;
    const int wid = t >> 5;
    const int wm  = wid >> 2;      // 0..3  (M: wm*32)
    const int wn  = wid & 3;       // 0..3  (N: wn*64)
    const uint32_t sb = smem_u32(smem);

    const int b = blockIdx.z;
    const size_t aRow0 = (size_t)b * aRows + blockIdx.y * 128;
    const size_t bRow0 = (size_t)b * 2048  + blockIdx.x * 256;

    uint32_t aBase[2], bBase[4];
    {
        int ra = wm * 32 + (l & 7) + ((l >> 3) & 1) * 8;
        #pragma unroll
        for (int mf = 0; mf < 2; mf++) aBase[mf] = sb + (uint32_t)(ra + mf * 16) * 128;
        int rb = wn * 64 + (l & 7) + ((l >> 4) & 1) * 8;
        #pragma unroll
        for (int p = 0; p < 4; p++)  bBase[p]  = sb + AV * A_SZ + (uint32_t)(rb + p * 16) * 128;
    }
    const int aColBit = (l >> 4) & 1;
    const int bColBit = (l >> 3) & 1;
    const int r7 = l & 7;

    float acc[2][8][4];
    #pragma unroll
    for (int i = 0; i < 2; i++)
        #pragma unroll
        for (int j = 0; j < 8; j++)
            #pragma unroll
            for (int q = 0; q < 4; q++) acc[i][j][q] = 0.f;

    auto load_stage = [&](int st, int k0) {
        uint32_t base = sb + (uint32_t)st * STAGE;
        const __half* asrc[2] = {Ahi, Alo};
        #pragma unroll
        for (int v = 0; v < AV; v++) {
            #pragma unroll
            for (int j = 0; j < 2; j++) {
                int idx = j * 512 + t;
                int row = idx >> 3, u = idx & 7;           // u = 16B unit (8 fp16)
                const __half* g = asrc[v] + (aRow0 + row) * (size_t)K + k0 + u * 8;
                cpasync16(base + v * A_SZ + (uint32_t)row * 128 + (uint32_t)((u ^ (row & 7)) << 4), g);
            }
        }
        const __half* bsrc[2] = {Bhi, Blo};
        #pragma unroll
        for (int v = 0; v < BV; v++) {
            #pragma unroll
            for (int j = 0; j < 4; j++) {
                int idx = j * 512 + t;
                int row = idx >> 3, u = idx & 7;
                const __half* g = bsrc[v] + (bRow0 + row) * (size_t)K + k0 + u * 8;
                cpasync16(base + AV * A_SZ + v * B_SZ + (uint32_t)row * 128 + (uint32_t)((u ^ (row & 7)) << 4), g);
            }
        }
    };

    #pragma unroll
    for (int s = 0; s < STAGES - 1; s++) {
        load_stage(s, s * 64);
        cp_commit();
    }

    for (int c = 0; c < NS; c++) {
        asm volatile("cp.async.wait_group %0;" :: "n"(STAGES - 2) : "memory");
        __syncthreads();

        const int ps = c + STAGES - 1;
        if (ps < NS) load_stage(ps % STAGES, ps * 64);
        cp_commit();

        const uint32_t stb = (uint32_t)((c % STAGES) * STAGE);

        #pragma unroll
        for (int s = 0; s < 4; s++) {
            const uint32_t aswz = (uint32_t)(((2 * s + aColBit) ^ r7) << 4);
            const uint32_t bswz = (uint32_t)(((2 * s + bColBit) ^ r7) << 4);

            uint32_t ah[2][4], al[2][4];
            #pragma unroll
            for (int mf = 0; mf < 2; mf++) {
                ldsm4(ah[mf], aBase[mf] + stb + aswz);
                if (AV == 2) ldsm4(al[mf], aBase[mf] + stb + A_SZ + aswz);
            }
            #pragma unroll
            for (int p = 0; p < 4; p++) {
                uint32_t bh[4];
                ldsm4(bh, bBase[p] + stb + bswz);
                if (AV == 2 && BV == 2) {
                    uint32_t bl[4];
                    ldsm4(bl, bBase[p] + stb + B_SZ + bswz);
                    #pragma unroll
                    for (int mf = 0; mf < 2; mf++) {
                        mma16(acc[mf][2 * p],     ah[mf], bh[0], bh[1]);
                        mma16(acc[mf][2 * p],     ah[mf], bl[0], bl[1]);
                        mma16(acc[mf][2 * p],     al[mf], bh[0], bh[1]);
                        mma16(acc[mf][2 * p + 1], ah[mf], bh[2], bh[3]);
                        mma16(acc[mf][2 * p + 1], ah[mf], bl[2], bl[3]);
                        mma16(acc[mf][2 * p + 1], al[mf], bh[2], bh[3]);
                    }
                } else if (AV == 2) {
                    #pragma unroll
                    for (int mf = 0; mf < 2; mf++) {
                        mma16(acc[mf][2 * p],     ah[mf], bh[0], bh[1]);
                        mma16(acc[mf][2 * p],     al[mf], bh[0], bh[1]);
                        mma16(acc[mf][2 * p + 1], ah[mf], bh[2], bh[3]);
                        mma16(acc[mf][2 * p + 1], al[mf], bh[2], bh[3]);
                    }
                } else {
                    #pragma unroll
                    for (int mf = 0; mf < 2; mf++) {
                        mma16(acc[mf][2 * p],     ah[mf], bh[0], bh[1]);
                        mma16(acc[mf][2 * p + 1], ah[mf], bh[2], bh[3]);
                    }
                }
            }
        }
    }

    // ---- stats epilogue: per-tile column (max, sumexp) -> Part ----
    if (STATS) {
        float* sm = (float*)smem;           // [0,1024): per-warp col max; [1024,2048): col sums
        __syncthreads();                    // smem stages no longer needed

        // thread-local col max (cols: wn*64 + nf*8 + cc + {0,1})
        float cmax[16];
        #pragma unroll
        for (int nf = 0; nf < 8; nf++) {
            cmax[2*nf]   = fmaxf(fmaxf(acc[0][nf][0], acc[0][nf][2]),
                                 fmaxf(acc[1][nf][0], acc[1][nf][2]));
            cmax[2*nf+1] = fmaxf(fmaxf(acc[0][nf][1], acc[0][nf][3]),
                                 fmaxf(acc[1][nf][1], acc[1][nf][3]));
        }
        #pragma unroll
        for (int i = 0; i < 16; i++) {
            cmax[i] = fmaxf(cmax[i], __shfl_xor_sync(0xffffffffu, cmax[i], 4));
            cmax[i] = fmaxf(cmax[i], __shfl_xor_sync(0xffffffffu, cmax[i], 8));
            cmax[i] = fmaxf(cmax[i], __shfl_xor_sync(0xffffffffu, cmax[i], 16));
        }
        if (l < 4) {
            #pragma unroll
            for (int nf = 0; nf < 8; nf++) {
                int col = wn * 64 + nf * 8 + l * 2;
                sm[wm * 256 + col]     = cmax[2*nf];
                sm[wm * 256 + col + 1] = cmax[2*nf+1];
            }
        }
        __syncthreads();

        // cross-warp (wm) tile max for this thread's columns, then sum-exp
        const int cc = (l & 3) * 2;
        float csum[16];
        #pragma unroll
        for (int nf = 0; nf < 8; nf++) {
            int col = wn * 64 + nf * 8 + cc;
            float t0 = fmaxf(fmaxf(sm[col], sm[256 + col]),
                             fmaxf(sm[512 + col], sm[768 + col]));
            float t1 = fmaxf(fmaxf(sm[col + 1], sm[256 + col + 1]),
                             fmaxf(sm[512 + col + 1], sm[768 + col + 1]));
            csum[2*nf]   = __expf(acc[0][nf][0] - t0) + __expf(acc[0][nf][2] - t0)
                         + __expf(acc[1][nf][0] - t0) + __expf(acc[1][nf][2] - t0);
            csum[2*nf+1] = __expf(acc[0][nf][1] - t1) + __expf(acc[0][nf][3] - t1)
                         + __expf(acc[1][nf][1] - t1) + __expf(acc[1][nf][3] - t1);
        }
        #pragma unroll
        for (int i = 0; i < 16; i++) {
            csum[i] += __shfl_xor_sync(0xffffffffu, csum[i], 4);
            csum[i] += __shfl_xor_sync(0xffffffffu, csum[i], 8);
            csum[i] += __shfl_xor_sync(0xffffffffu, csum[i], 16);
        }
        if (l < 4) {
            #pragma unroll
            for (int nf = 0; nf < 8; nf++) {
                int col = wn * 64 + nf * 8 + l * 2;
                sm[1024 + wm * 256 + col]     = csum[2*nf];
                sm[1024 + wm * 256 + col + 1] = csum[2*nf+1];
            }
        }
        __syncthreads();

        if (t < 256) {
            float M = fmaxf(fmaxf(sm[t], sm[256 + t]), fmaxf(sm[512 + t], sm[768 + t]));
            float S = sm[1024 + t] + sm[1280 + t] + sm[1536 + t] + sm[1792 + t];
            Part[((size_t)b * 16 + blockIdx.y) * 2048 + blockIdx.x * 256 + t] =
                make_float2(M, S);
        }
    }

    // ---- score/output writes ----
    float* obase = Out + ((size_t)b * aRows + blockIdx.y * 128 + wm * 32) * 2048
                       + blockIdx.x * 256 + wn * 64;
    const int rr = l >> 2, cc2 = (l & 3) * 2;
    #pragma unroll
    for (int mf = 0; mf < 2; mf++) {
        #pragma unroll
        for (int nf = 0; nf < 8; nf++) {
            int r = mf * 16 + rr;
            int c = nf * 8 + cc2;
            *(float2*)(obase + (size_t)r * 2048 + c)       = make_float2(acc[mf][nf][0], acc[mf][nf][1]);
            *(float2*)(obase + (size_t)(r + 8) * 2048 + c) = make_float2(acc[mf][nf][2], acc[mf][nf][3]);
        }
    }
}

// ---------------------------------------------------------------------------
// combine per-tile partials -> (max, 1/sum) per (b, n1)
// ---------------------------------------------------------------------------
__global__ void reduce_stats_kernel(const float2* __restrict__ Part,
                                    float2* __restrict__ Stats)
{
    const int i = blockIdx.x * blockDim.x + threadIdx.x;   // b*2048 + n1
    const int b = i >> 11, n1 = i & 2047;
    const float2* p = Part + (size_t)b * 16 * 2048 + n1;
    float M = -FLT_MAX, S = 0.f;
    #pragma unroll
    for (int mt = 0; mt < 16; mt++) {
        float2 v = p[(size_t)mt * 2048];
        float mn = fmaxf(M, v.x);
        S = S * __expf(M - mn) + v.y * __expf(v.x - mn);
        M = mn;
    }
    Stats[i] = make_float2(M, 1.0f / S);
}

// ---------------------------------------------------------------------------
// Single-pass normalize: w = exp(v - M) * inv, in place; also writes fp16
// transposed copy Bt[b][n1][n2] via 32x32 smem tiles.
// block (32,8), grid (N1/32, B)
// ---------------------------------------------------------------------------
__global__ void normalize_kernel(float* __restrict__ S,
                                 const float2* __restrict__ Stats,
                                 __half* __restrict__ Bt)
{
    __shared__ float tile[32][33];
    const int x = threadIdx.x, y = threadIdx.y;
    const int b = blockIdx.y;
    const int n1b = blockIdx.x * 32;
    float* Sb = S + (size_t)b * N2_ * N1_ + n1b + x;

    const float2 st = Stats[b * 2048 + n1b + x];
    const float M = st.x, inv = st.y;

    for (int t2 = 0; t2 < N2_; t2 += 32) {
        #pragma unroll
        for (int k = 0; k < 4; k++) {
            int r = t2 + y + 8 * k;
            float v = Sb[(size_t)r * N1_];
            float w = __expf(v - M) * inv;
            Sb[(size_t)r * N1_] = w;
            tile[y + 8 * k][x] = w;
        }
        __syncthreads();
        #pragma unroll
        for (int k = 0; k < 4; k++) {
            int ry = y + 8 * k;                       // local n1
            float w = tile[x][ry];
            Bt[((size_t)b * N1_ + n1b + ry) * N2_ + t2 + x] = __float2half_rn(w);
        }
        __syncthreads();
    }
}

// ---------------------------------------------------------------------------
// launch
// ---------------------------------------------------------------------------
extern "C" void kernel_launch(void* const* d_in, const int* in_sizes, int n_in,
                              void* d_out, int out_size)
{
    (void)in_sizes; (void)n_in; (void)out_size;
    const float* RI1 = (const float*)d_in[0];   // [B][C][N1]
    const float* RI2 = (const float*)d_in[1];   // [B][C][N2]
    const float* RE2 = (const float*)d_in[2];   // [B][D][N2]

    float* out   = (float*)d_out;
    float* embed = out;                                  // [B][D][N1]
    float* attn  = out + (size_t)B_ * D_ * N1_;          // [B][N2][N1]

    void *ri1h, *ri1l, *ri2h, *ri2l, *re2, *bt, *part, *stats;
    cudaGetSymbolAddress(&ri1h, g_ri1t_hi);
    cudaGetSymbolAddress(&ri1l, g_ri1t_lo);
    cudaGetSymbolAddress(&ri2h, g_ri2t_hi);
    cudaGetSymbolAddress(&ri2l, g_ri2t_lo);
    cudaGetSymbolAddress(&re2,  g_re2);
    cudaGetSymbolAddress(&bt,   g_bt);
    cudaGetSymbolAddress(&part, g_part);
    cudaGetSymbolAddress(&stats, g_stats);

    constexpr int SMEM1 = 2 * (2 * 128 * 128 + 2 * 256 * 128);   // 196608
    constexpr int SMEM2 = 4 * (1 * 128 * 128 + 1 * 256 * 128);   // 196608
    cudaFuncSetAttribute((const void*)gemm_mma<512, 2, 2, 2, true>,
                         cudaFuncAttributeMaxDynamicSharedMemorySize, SMEM1);
    cudaFuncSetAttribute((const void*)gemm_mma<2048, 1, 1, 4, false>,
                         cudaFuncAttributeMaxDynamicSharedMemorySize, SMEM2);

    dim3 tb(32, 8);
    tsplit_kernel<<<dim3(N1_ / 32, C_ / 32, B_), tb>>>(
        RI1, (__half*)ri1h, (__half*)ri1l);
    tsplit_kernel<<<dim3(N2_ / 32, C_ / 32, B_), tb>>>(
        RI2, (__half*)ri2h, (__half*)ri2l);
    hconv_kernel<<<(B_ * D_ * N2_ / 4) / 256, 256>>>(
        (const float4*)RE2, (__half*)re2);

    // GEMM1 + per-tile softmax stats
    gemm_mma<512, 2, 2, 2, true><<<dim3(N1_ / 256, N2_ / 128, B_), 512, SMEM1>>>(
        (const __half*)ri2h, (const __half*)ri2l,
        (const __half*)ri1h, (const __half*)ri1l, attn, (float2*)part, N2_);

    reduce_stats_kernel<<<(B_ * N1_) / 256, 256>>>(
        (const float2*)part, (float2*)stats);

    normalize_kernel<<<dim3(N1_ / 32, B_), tb>>>(
        attn, (const float2*)stats, (__half*)bt);

    // GEMM2: embed[b][d][n1] = RE2(fp16) x attnT(fp16), 1 product, K=2048
    gemm_mma<2048, 1, 1, 4, false><<<dim3(N1_ / 256, D_ / 128, B_), 512, SMEM2>>>(
        (const __half*)re2, nullptr,
        (const __half*)bt, nullptr, embed, nullptr, D_);
}

// round 11
// speedup vs baseline: 3.7976x; 1.0331x over previous
#include <cuda_runtime.h>
#include <cuda_fp16.h>
#include <cstdint>
#include <cfloat>

#define B_   16
#define C_   512
#define D_   512
#define N1_  2048
#define N2_  2048

// ---------------------------------------------------------------------------
// scratch (__device__ globals: allocation-free), fp16 operands
// ---------------------------------------------------------------------------
__device__ __align__(16) __half g_ri1t_hi[16 * 2048 * 512];
__device__ __align__(16) __half g_ri1t_lo[16 * 2048 * 512];
__device__ __align__(16) __half g_ri2t_hi[16 * 2048 * 512];
__device__ __align__(16) __half g_ri2t_lo[16 * 2048 * 512];
__device__ __align__(16) __half g_re2    [16 * 512 * 2048];
__device__ __align__(16) __half g_bt     [16 * 2048 * 2048];   // attn^T fp16
__device__ __align__(16) float2 g_part   [16 * 16 * 2048];     // per-tile (max, sumexp)

// ---------------------------------------------------------------------------
// helpers
// ---------------------------------------------------------------------------
__device__ __forceinline__ uint32_t smem_u32(const void* p) {
    uint32_t a;
    asm("{ .reg .u64 t; cvta.to.shared.u64 t, %1; cvt.u32.u64 %0, t; }" : "=r"(a) : "l"(p));
    return a;
}
__device__ __forceinline__ void cpasync16(uint32_t dst, const void* src) {
    asm volatile("cp.async.cg.shared.global [%0], [%1], 16;" :: "r"(dst), "l"(src));
}
__device__ __forceinline__ void cp_commit() {
    asm volatile("cp.async.commit_group;" ::: "memory");
}
__device__ __forceinline__ void ldsm4(uint32_t* r, uint32_t addr) {
    asm volatile("ldmatrix.sync.aligned.m8n8.x4.shared.b16 {%0,%1,%2,%3}, [%4];"
                 : "=r"(r[0]), "=r"(r[1]), "=r"(r[2]), "=r"(r[3]) : "r"(addr));
}
__device__ __forceinline__ void mma16(float* d, const uint32_t* a, uint32_t b0, uint32_t b1) {
    asm volatile("mma.sync.aligned.m16n8k16.row.col.f32.f16.f16.f32 "
                 "{%0,%1,%2,%3}, {%4,%5,%6,%7}, {%8,%9}, {%0,%1,%2,%3};"
                 : "+f"(d[0]), "+f"(d[1]), "+f"(d[2]), "+f"(d[3])
                 : "r"(a[0]), "r"(a[1]), "r"(a[2]), "r"(a[3]), "r"(b0), "r"(b1));
}
__device__ __forceinline__ void hsplit(float x, __half& h, __half& l) {
    h = __float2half_rn(x);
    l = __float2half_rn(x - __half2float(h));
}

// ---------------------------------------------------------------------------
// fused transpose + fp16 split for RI1 and RI2:
// X[b][C][N] -> Thi/Tlo[b][N][C].  64c x 32n tiles, half2 writes.
// grid (N/32, C/64, 2*B), block (32,8)
// ---------------------------------------------------------------------------
__global__ void tsplit2_kernel(const float* __restrict__ X1, const float* __restrict__ X2,
                               __half* __restrict__ T1h, __half* __restrict__ T1l,
                               __half* __restrict__ T2h, __half* __restrict__ T2l)
{
    __shared__ float tile[64][33];
    const int z = blockIdx.z;
    const int b = z & 15, sel = z >> 4;
    const float* X = sel ? X2 : X1;
    __half* Th = sel ? T2h : T1h;
    __half* Tl = sel ? T2l : T1l;

    const int n0 = blockIdx.x * 32, c0 = blockIdx.y * 64;
    const int x = threadIdx.x, y = threadIdx.y;

    const size_t ib = (size_t)b * C_ * N1_;
    #pragma unroll
    for (int i = 0; i < 8; i++) {
        int cl = y + 8 * i;
        tile[cl][x] = X[ib + (size_t)(c0 + cl) * N1_ + n0 + x];
    }
    __syncthreads();

    const size_t ob = (size_t)b * N1_ * C_;
    #pragma unroll
    for (int i = 0; i < 4; i++) {
        int nl = y + 8 * i;
        float v0 = tile[2 * x][nl];
        float v1 = tile[2 * x + 1][nl];
        __half h0, l0, h1, l1;
        hsplit(v0, h0, l0); hsplit(v1, h1, l1);
        size_t o = ob + (size_t)(n0 + nl) * C_ + c0 + 2 * x;
        *(__half2*)(Th + o) = __half2(h0, h1);
        *(__half2*)(Tl + o) = __half2(l0, l1);
    }
}

// plain fp16 convert (RE2): K-major already
__global__ void hconv_kernel(const float4* __restrict__ src,
                             __half* __restrict__ dst)
{
    const int i = blockIdx.x * blockDim.x + threadIdx.x;
    float4 v = src[i];
    __half2* D = (__half2*)(dst + (size_t)i * 4);
    D[0] = __half2(__float2half_rn(v.x), __float2half_rn(v.y));
    D[1] = __half2(__float2half_rn(v.z), __float2half_rn(v.w));
}

// ---------------------------------------------------------------------------
// fp16 GEMM via mma.sync m16n8k16. Single-sync multistage pipeline.
// Out[b*aRows + m][n] (n-stride 2048) = sum_k A[row][k] * B[row][k]
// AV/BV = split versions per operand (AV2,BV2: 3 products; AV1,BV1: 1).
// Block 128(M) x 256(N), 16 warps, warptile 32x64, k-chunk 64.
// STATS: epilogue emits per-tile column (max, sumexp) into Part,
//        using a dedicated smem region past the pipeline stages.
// ---------------------------------------------------------------------------
template<int K, int AV, int BV, int STAGES, bool STATS>
__global__ __launch_bounds__(512)
void gemm_mma(const __half* __restrict__ Ahi, const __half* __restrict__ Alo,
              const __half* __restrict__ Bhi, const __half* __restrict__ Blo,
              float* __restrict__ Out, float2* __restrict__ Part, int aRows)
{
    extern __shared__ __align__(128) char smem[];
    constexpr int A_SZ  = 128 * 128;              // bytes per A version
    constexpr int B_SZ  = 256 * 128;              // bytes per B version
    constexpr int STAGE = AV * A_SZ + BV * B_SZ;
    constexpr int NS    = K / 64;                 // k-chunk = 64 fp16 = 128B row

    const int t   = threadIdx.x;
    const int l   = t & 31;
    const int wid = t >> 5;
    const int wm  = wid >> 2;      // 0..3  (M: wm*32)
    const int wn  = wid & 3;       // 0..3  (N: wn*64)
    const uint32_t sb = smem_u32(smem);

    const int b = blockIdx.z;
    const size_t aRow0 = (size_t)b * aRows + blockIdx.y * 128;
    const size_t bRow0 = (size_t)b * 2048  + blockIdx.x * 256;

    uint32_t aBase[2], bBase[4];
    {
        int ra = wm * 32 + (l & 7) + ((l >> 3) & 1) * 8;
        #pragma unroll
        for (int mf = 0; mf < 2; mf++) aBase[mf] = sb + (uint32_t)(ra + mf * 16) * 128;
        int rb = wn * 64 + (l & 7) + ((l >> 4) & 1) * 8;
        #pragma unroll
        for (int p = 0; p < 4; p++)  bBase[p]  = sb + AV * A_SZ + (uint32_t)(rb + p * 16) * 128;
    }
    const int aColBit = (l >> 4) & 1;
    const int bColBit = (l >> 3) & 1;
    const int r7 = l & 7;

    float acc[2][8][4];
    #pragma unroll
    for (int i = 0; i < 2; i++)
        #pragma unroll
        for (int j = 0; j < 8; j++)
            #pragma unroll
            for (int q = 0; q < 4; q++) acc[i][j][q] = 0.f;

    auto load_stage = [&](int st, int k0) {
        uint32_t base = sb + (uint32_t)st * STAGE;
        const __half* asrc[2] = {Ahi, Alo};
        #pragma unroll
        for (int v = 0; v < AV; v++) {
            #pragma unroll
            for (int j = 0; j < 2; j++) {
                int idx = j * 512 + t;
                int row = idx >> 3, u = idx & 7;           // u = 16B unit (8 fp16)
                const __half* g = asrc[v] + (aRow0 + row) * (size_t)K + k0 + u * 8;
                cpasync16(base + v * A_SZ + (uint32_t)row * 128 + (uint32_t)((u ^ (row & 7)) << 4), g);
            }
        }
        const __half* bsrc[2] = {Bhi, Blo};
        #pragma unroll
        for (int v = 0; v < BV; v++) {
            #pragma unroll
            for (int j = 0; j < 4; j++) {
                int idx = j * 512 + t;
                int row = idx >> 3, u = idx & 7;
                const __half* g = bsrc[v] + (bRow0 + row) * (size_t)K + k0 + u * 8;
                cpasync16(base + AV * A_SZ + v * B_SZ + (uint32_t)row * 128 + (uint32_t)((u ^ (row & 7)) << 4), g);
            }
        }
    };

    #pragma unroll
    for (int s = 0; s < STAGES - 1; s++) {
        load_stage(s, s * 64);
        cp_commit();
    }

    for (int c = 0; c < NS; c++) {
        asm volatile("cp.async.wait_group %0;" :: "n"(STAGES - 2) : "memory");
        __syncthreads();

        const int ps = c + STAGES - 1;
        if (ps < NS) load_stage(ps % STAGES, ps * 64);
        cp_commit();

        const uint32_t stb = (uint32_t)((c % STAGES) * STAGE);

        #pragma unroll
        for (int s = 0; s < 4; s++) {
            const uint32_t aswz = (uint32_t)(((2 * s + aColBit) ^ r7) << 4);
            const uint32_t bswz = (uint32_t)(((2 * s + bColBit) ^ r7) << 4);

            uint32_t ah[2][4], al[2][4];
            #pragma unroll
            for (int mf = 0; mf < 2; mf++) {
                ldsm4(ah[mf], aBase[mf] + stb + aswz);
                if (AV == 2) ldsm4(al[mf], aBase[mf] + stb + A_SZ + aswz);
            }
            #pragma unroll
            for (int p = 0; p < 4; p++) {
                uint32_t bh[4];
                ldsm4(bh, bBase[p] + stb + bswz);
                if (AV == 2 && BV == 2) {
                    uint32_t bl[4];
                    ldsm4(bl, bBase[p] + stb + B_SZ + bswz);
                    #pragma unroll
                    for (int mf = 0; mf < 2; mf++) {
                        mma16(acc[mf][2 * p],     ah[mf], bh[0], bh[1]);
                        mma16(acc[mf][2 * p],     ah[mf], bl[0], bl[1]);
                        mma16(acc[mf][2 * p],     al[mf], bh[0], bh[1]);
                        mma16(acc[mf][2 * p + 1], ah[mf], bh[2], bh[3]);
                        mma16(acc[mf][2 * p + 1], ah[mf], bl[2], bl[3]);
                        mma16(acc[mf][2 * p + 1], al[mf], bh[2], bh[3]);
                    }
                } else if (AV == 2) {
                    #pragma unroll
                    for (int mf = 0; mf < 2; mf++) {
                        mma16(acc[mf][2 * p],     ah[mf], bh[0], bh[1]);
                        mma16(acc[mf][2 * p],     al[mf], bh[0], bh[1]);
                        mma16(acc[mf][2 * p + 1], ah[mf], bh[2], bh[3]);
                        mma16(acc[mf][2 * p + 1], al[mf], bh[2], bh[3]);
                    }
                } else {
                    #pragma unroll
                    for (int mf = 0; mf < 2; mf++) {
                        mma16(acc[mf][2 * p],     ah[mf], bh[0], bh[1]);
                        mma16(acc[mf][2 * p + 1], ah[mf], bh[2], bh[3]);
                    }
                }
            }
        }
    }

    // ---- score writes first (fire-and-forget; stats math hides them) ----
    float* obase = Out + ((size_t)b * aRows + blockIdx.y * 128 + wm * 32) * 2048
                       + blockIdx.x * 256 + wn * 64;
    const int rr = l >> 2, cc2 = (l & 3) * 2;
    #pragma unroll
    for (int mf = 0; mf < 2; mf++) {
        #pragma unroll
        for (int nf = 0; nf < 8; nf++) {
            int r = mf * 16 + rr;
            int c = nf * 8 + cc2;
            *(float2*)(obase + (size_t)r * 2048 + c)       = make_float2(acc[mf][nf][0], acc[mf][nf][1]);
            *(float2*)(obase + (size_t)(r + 8) * 2048 + c) = make_float2(acc[mf][nf][2], acc[mf][nf][3]);
        }
    }

    // ---- stats epilogue: per-tile column (max, sumexp) -> Part ----
    if (STATS) {
        float* sm = (float*)(smem + STAGES * STAGE);   // dedicated 8KB region

        float cmax[16];
        #pragma unroll
        for (int nf = 0; nf < 8; nf++) {
            cmax[2*nf]   = fmaxf(fmaxf(acc[0][nf][0], acc[0][nf][2]),
                                 fmaxf(acc[1][nf][0], acc[1][nf][2]));
            cmax[2*nf+1] = fmaxf(fmaxf(acc[0][nf][1], acc[0][nf][3]),
                                 fmaxf(acc[1][nf][1], acc[1][nf][3]));
        }
        #pragma unroll
        for (int i = 0; i < 16; i++) {
            cmax[i] = fmaxf(cmax[i], __shfl_xor_sync(0xffffffffu, cmax[i], 4));
            cmax[i] = fmaxf(cmax[i], __shfl_xor_sync(0xffffffffu, cmax[i], 8));
            cmax[i] = fmaxf(cmax[i], __shfl_xor_sync(0xffffffffu, cmax[i], 16));
        }
        if (l < 4) {
            #pragma unroll
            for (int nf = 0; nf < 8; nf++) {
                int col = wn * 64 + nf * 8 + l * 2;
                sm[wm * 256 + col]     = cmax[2*nf];
                sm[wm * 256 + col + 1] = cmax[2*nf+1];
            }
        }
        __syncthreads();

        const int cc = (l & 3) * 2;
        float csum[16];
        #pragma unroll
        for (int nf = 0; nf < 8; nf++) {
            int col = wn * 64 + nf * 8 + cc;
            float t0 = fmaxf(fmaxf(sm[col], sm[256 + col]),
                             fmaxf(sm[512 + col], sm[768 + col]));
            float t1 = fmaxf(fmaxf(sm[col + 1], sm[256 + col + 1]),
                             fmaxf(sm[512 + col + 1], sm[768 + col + 1]));
            csum[2*nf]   = __expf(acc[0][nf][0] - t0) + __expf(acc[0][nf][2] - t0)
                         + __expf(acc[1][nf][0] - t0) + __expf(acc[1][nf][2] - t0);
            csum[2*nf+1] = __expf(acc[0][nf][1] - t1) + __expf(acc[0][nf][3] - t1)
                         + __expf(acc[1][nf][1] - t1) + __expf(acc[1][nf][3] - t1);
        }
        #pragma unroll
        for (int i = 0; i < 16; i++) {
            csum[i] += __shfl_xor_sync(0xffffffffu, csum[i], 4);
            csum[i] += __shfl_xor_sync(0xffffffffu, csum[i], 8);
            csum[i] += __shfl_xor_sync(0xffffffffu, csum[i], 16);
        }
        if (l < 4) {
            #pragma unroll
            for (int nf = 0; nf < 8; nf++) {
                int col = wn * 64 + nf * 8 + l * 2;
                sm[1024 + wm * 256 + col]     = csum[2*nf];
                sm[1024 + wm * 256 + col + 1] = csum[2*nf+1];
            }
        }
        __syncthreads();

        if (t < 256) {
            float M = fmaxf(fmaxf(sm[t], sm[256 + t]), fmaxf(sm[512 + t], sm[768 + t]));
            float S = sm[1024 + t] + sm[1280 + t] + sm[1536 + t] + sm[1792 + t];
            Part[((size_t)b * 16 + blockIdx.y) * 2048 + blockIdx.x * 256 + t] =
                make_float2(M, S);
        }
    }
}

// ---------------------------------------------------------------------------
// Fused stats-reduce + single-pass normalize + fp16 transpose.
// grid (N1/128, B), block (32,8).  Each block: 128 n1 cols, all 2048 n2.
// ---------------------------------------------------------------------------
__global__ void normalize_kernel(float* __restrict__ S,
                                 const float2* __restrict__ Part,
                                 __half* __restrict__ Bt)
{
    __shared__ float tile[64][129];
    __shared__ float smM[128], smI[128];

    const int x = threadIdx.x, y = threadIdx.y;
    const int t = y * 32 + x;
    const int wid2 = t >> 5, l = t & 31;
    const int b = blockIdx.y;
    const int n1b = blockIdx.x * 128;

    // combine 16 per-tile partials for this block's columns
    if (t < 128) {
        const float2* p = Part + (size_t)b * 16 * 2048 + n1b + t;
        float M = -FLT_MAX, Sm = 0.f;
        #pragma unroll
        for (int mt = 0; mt < 16; mt++) {
            float2 v = p[(size_t)mt * 2048];
            float mn = fmaxf(M, v.x);
            Sm = Sm * __expf(M - mn) + v.y * __expf(v.x - mn);
            M = mn;
        }
        smM[t] = M; smI[t] = 1.0f / Sm;
    }
    __syncthreads();

    float M4[4], I4[4];
    #pragma unroll
    for (int j = 0; j < 4; j++) { M4[j] = smM[4 * x + j]; I4[j] = smI[4 * x + j]; }

    float* Sb = S + (size_t)b * N2_ * N1_;
    __half* Bb = Bt + (size_t)b * N1_ * N2_;

    for (int t2 = 0; t2 < N2_; t2 += 64) {
        #pragma unroll
        for (int k = 0; k < 8; k++) {
            int rl = y + 8 * k;
            float4* gp = (float4*)(Sb + (size_t)(t2 + rl) * N1_ + n1b + 4 * x);
            float4 v = *gp;
            v.x = __expf(v.x - M4[0]) * I4[0];
            v.y = __expf(v.y - M4[1]) * I4[1];
            v.z = __expf(v.z - M4[2]) * I4[2];
            v.w = __expf(v.w - M4[3]) * I4[3];
            *gp = v;
            tile[rl][4 * x]     = v.x;
            tile[rl][4 * x + 1] = v.y;
            tile[rl][4 * x + 2] = v.z;
            tile[rl][4 * x + 3] = v.w;
        }
        __syncthreads();
        #pragma unroll
        for (int i = 0; i < 16; i++) {
            int n1l = 8 * i + wid2;
            __half2 h = __half2(__float2half_rn(tile[2 * l][n1l]),
                                __float2half_rn(tile[2 * l + 1][n1l]));
            *(__half2*)(Bb + (size_t)(n1b + n1l) * N2_ + t2 + 2 * l) = h;
        }
        __syncthreads();
    }
}

// ---------------------------------------------------------------------------
// launch
// ---------------------------------------------------------------------------
extern "C" void kernel_launch(void* const* d_in, const int* in_sizes, int n_in,
                              void* d_out, int out_size)
{
    (void)in_sizes; (void)n_in; (void)out_size;
    const float* RI1 = (const float*)d_in[0];   // [B][C][N1]
    const float* RI2 = (const float*)d_in[1];   // [B][C][N2]
    const float* RE2 = (const float*)d_in[2];   // [B][D][N2]

    float* out   = (float*)d_out;
    float* embed = out;                                  // [B][D][N1]
    float* attn  = out + (size_t)B_ * D_ * N1_;          // [B][N2][N1]

    void *ri1h, *ri1l, *ri2h, *ri2l, *re2, *bt, *part;
    cudaGetSymbolAddress(&ri1h, g_ri1t_hi);
    cudaGetSymbolAddress(&ri1l, g_ri1t_lo);
    cudaGetSymbolAddress(&ri2h, g_ri2t_hi);
    cudaGetSymbolAddress(&ri2l, g_ri2t_lo);
    cudaGetSymbolAddress(&re2,  g_re2);
    cudaGetSymbolAddress(&bt,   g_bt);
    cudaGetSymbolAddress(&part, g_part);

    constexpr int SMEM1 = 2 * (2 * 128 * 128 + 2 * 256 * 128) + 8192;  // 204800
    constexpr int SMEM2 = 4 * (1 * 128 * 128 + 1 * 256 * 128);         // 196608
    cudaFuncSetAttribute((const void*)gemm_mma<512, 2, 2, 2, true>,
                         cudaFuncAttributeMaxDynamicSharedMemorySize, SMEM1);
    cudaFuncSetAttribute((const void*)gemm_mma<2048, 1, 1, 4, false>,
                         cudaFuncAttributeMaxDynamicSharedMemorySize, SMEM2);

    dim3 tb(32, 8);
    tsplit2_kernel<<<dim3(N1_ / 32, C_ / 64, 2 * B_), tb>>>(
        RI1, RI2,
        (__half*)ri1h, (__half*)ri1l, (__half*)ri2h, (__half*)ri2l);
    hconv_kernel<<<(B_ * D_ * N2_ / 4) / 256, 256>>>(
        (const float4*)RE2, (__half*)re2);

    // GEMM1 + per-tile softmax stats
    gemm_mma<512, 2, 2, 2, true><<<dim3(N1_ / 256, N2_ / 128, B_), 512, SMEM1>>>(
        (const __half*)ri2h, (const __half*)ri2l,
        (const __half*)ri1h, (const __half*)ri1l, attn, (float2*)part, N2_);

    // fused stats-reduce + normalize + fp16 transpose
    normalize_kernel<<<dim3(N1_ / 128, B_), tb>>>(
        attn, (const float2*)part, (__half*)bt);

    // GEMM2: embed[b][d][n1] = RE2(fp16) x attnT(fp16), 1 product, K=2048
    gemm_mma<2048, 1, 1, 4, false><<<dim3(N1_ / 256, D_ / 128, B_), 512, SMEM2>>>(
        (const __half*)re2, nullptr,
        (const __half*)bt, nullptr, embed, nullptr, D_);
}